// round 1
// baseline (speedup 1.0000x reference)
#include <cuda_runtime.h>
#include <cuda_bf16.h>
#include <math.h>
#include <stdint.h>

// Problem constants
#define BB 2
#define LL 2048
#define HH 16
#define DD 64
#define DMODEL 1024
#define MROWS (BB*LL)          // 4096

// ---------------- scratch (device globals: no allocations allowed) -------------
__device__ float g_Q[(size_t)MROWS * DMODEL];   // (b,l, h*d)
__device__ float g_K[(size_t)MROWS * DMODEL];
__device__ float g_V[(size_t)MROWS * DMODEL];
__device__ float g_A[(size_t)MROWS * DMODEL];   // attention output (b,l, h*d)

// =============================== SGEMM ========================================
// C[M,N] = A[M,K] * B[K,N] (+ bias). 128x128 tile, BK=16, 256 thr, 8x8 microtile.
#define GBM 128
#define GBN 128
#define GBK 16
#define GPAD 4

template <bool HAS_BIAS>
__global__ __launch_bounds__(256)
void sgemm_kernel(const float* __restrict__ A, const float* __restrict__ B,
                  float* __restrict__ C, const float* __restrict__ bias,
                  int M, int N, int K)
{
    __shared__ float As[GBK][GBM + GPAD];   // A tile, transposed (k, m)
    __shared__ float Bs[GBK][GBN + GPAD];   // B tile (k, n)

    const int tid = threadIdx.x;
    const int bm = blockIdx.y * GBM;
    const int bn = blockIdx.x * GBN;
    const int tr = tid >> 4;      // 0..15 : rows tr*8 .. tr*8+7
    const int tc = tid & 15;      // 0..15 : cols tc*8 .. tc*8+7

    float acc[8][8];
#pragma unroll
    for (int i = 0; i < 8; ++i)
#pragma unroll
        for (int j = 0; j < 8; ++j) acc[i][j] = 0.0f;

    for (int k0 = 0; k0 < K; k0 += GBK) {
        // load A tile: 128x16 floats = 512 float4, 2 per thread
#pragma unroll
        for (int t = 0; t < 2; ++t) {
            int idx = tid + t * 256;
            int r = idx >> 2;
            int c4 = (idx & 3) << 2;
            float4 v = *(const float4*)(A + (size_t)(bm + r) * K + k0 + c4);
            As[c4 + 0][r] = v.x;
            As[c4 + 1][r] = v.y;
            As[c4 + 2][r] = v.z;
            As[c4 + 3][r] = v.w;
        }
        // load B tile: 16x128 floats = 512 float4, 2 per thread
#pragma unroll
        for (int t = 0; t < 2; ++t) {
            int idx = tid + t * 256;
            int r = idx >> 5;
            int c4 = (idx & 31) << 2;
            float4 v = *(const float4*)(B + (size_t)(k0 + r) * N + bn + c4);
            *(float4*)(&Bs[r][c4]) = v;
        }
        __syncthreads();

#pragma unroll
        for (int kk = 0; kk < GBK; ++kk) {
            float a[8], b[8];
            *(float4*)(a)     = *(const float4*)(&As[kk][tr * 8]);
            *(float4*)(a + 4) = *(const float4*)(&As[kk][tr * 8 + 4]);
            *(float4*)(b)     = *(const float4*)(&Bs[kk][tc * 8]);
            *(float4*)(b + 4) = *(const float4*)(&Bs[kk][tc * 8 + 4]);
#pragma unroll
            for (int i = 0; i < 8; ++i)
#pragma unroll
                for (int j = 0; j < 8; ++j)
                    acc[i][j] += a[i] * b[j];
        }
        __syncthreads();
    }

    // epilogue
#pragma unroll
    for (int i = 0; i < 8; ++i) {
        int row = bm + tr * 8 + i;
        float* crow = C + (size_t)row * N + bn + tc * 8;
#pragma unroll
        for (int j4 = 0; j4 < 8; j4 += 4) {
            float4 v;
            v.x = acc[i][j4 + 0];
            v.y = acc[i][j4 + 1];
            v.z = acc[i][j4 + 2];
            v.w = acc[i][j4 + 3];
            if (HAS_BIAS) {
                const float* brow = bias + bn + tc * 8 + j4;
                v.x += brow[0]; v.y += brow[1]; v.z += brow[2]; v.w += brow[3];
            }
            *(float4*)(crow + j4) = v;
        }
    }
}

// ============================ Flash attention =================================
// One CTA: 128 query rows of one (b,h), loops over 64-key blocks (causal bound),
// online softmax in fp32, applies the real attention/padding masks.
#define FBM 128
#define FBN 64
#define QPAD 65   // row stride (padding) in smem

__global__ __launch_bounds__(256)
void flash_kernel(const float* __restrict__ Qg, const float* __restrict__ Kg,
                  const float* __restrict__ Vg, const int* __restrict__ am,
                  const int* __restrict__ pmk, float* __restrict__ Og)
{
    extern __shared__ float sm[];
    float* Qs = sm;                         // 128 x QPAD
    float* Ks = Qs + FBM * QPAD;            // 64 x QPAD
    float* Vs = Ks + FBN * QPAD;            // 64 x QPAD
    float* Ps = Vs + FBN * QPAD;            // 128 x QPAD

    const int tid = threadIdx.x;
    const int qb = (int)gridDim.x - 1 - (int)blockIdx.x;  // heavy blocks first
    const int h = blockIdx.y;
    const int b = blockIdx.z;
    const int tr = tid >> 4;   // 0..15 -> rows tr*8..tr*8+7
    const int tc = tid & 15;   // 0..15 -> cols tc*4..tc*4+3

    const float scale = 0.125f;   // 1/sqrt(64)
    const int x0 = qb * FBM;

    // load Q tile (pre-scaled): 8192 floats = 2048 float4, 8 per thread
#pragma unroll
    for (int t = 0; t < 8; ++t) {
        int idx = tid + t * 256;
        int r = idx >> 4;
        int c4 = (idx & 15) << 2;
        float4 v = *(const float4*)(Qg + (size_t)(b * LL + x0 + r) * DMODEL + h * DD + c4);
        float* dst = Qs + r * QPAD + c4;
        dst[0] = v.x * scale;
        dst[1] = v.y * scale;
        dst[2] = v.z * scale;
        dst[3] = v.w * scale;
    }

    float m_i[8], l_i[8], o[8][4];
#pragma unroll
    for (int i = 0; i < 8; ++i) {
        m_i[i] = -3.0e38f;
        l_i[i] = 0.0f;
#pragma unroll
        for (int j = 0; j < 4; ++j) o[i][j] = 0.0f;
    }

    const int nkb = 2 * qb + 2;   // causal loop bound (mask is tril by construction)
    for (int kb = 0; kb < nkb; ++kb) {
        const int z0 = kb * FBN;
        __syncthreads();   // protect Ks/Vs (and Qs on first iter)

        // load K and V tiles: 64x64 each = 1024 float4 each, 4 per thread
#pragma unroll
        for (int t = 0; t < 4; ++t) {
            int idx = tid + t * 256;
            int r = idx >> 4;
            int c4 = (idx & 15) << 2;
            size_t goff = (size_t)(b * LL + z0 + r) * DMODEL + h * DD + c4;
            float4 kv = *(const float4*)(Kg + goff);
            float4 vv = *(const float4*)(Vg + goff);
            float* kd = Ks + r * QPAD + c4;
            float* vd = Vs + r * QPAD + c4;
            kd[0] = kv.x; kd[1] = kv.y; kd[2] = kv.z; kd[3] = kv.w;
            vd[0] = vv.x; vd[1] = vv.y; vd[2] = vv.z; vd[3] = vv.w;
        }
        __syncthreads();

        // S = (Q*scale) @ K^T   (8x4 per thread)
        float s[8][4];
#pragma unroll
        for (int i = 0; i < 8; ++i)
#pragma unroll
            for (int j = 0; j < 4; ++j) s[i][j] = 0.0f;

#pragma unroll 4
        for (int d = 0; d < DD; ++d) {
            float q[8], kk[4];
#pragma unroll
            for (int i = 0; i < 8; ++i) q[i] = Qs[(tr * 8 + i) * QPAD + d];
#pragma unroll
            for (int j = 0; j < 4; ++j) kk[j] = Ks[(tc * 4 + j) * QPAD + d];
#pragma unroll
            for (int i = 0; i < 8; ++i)
#pragma unroll
                for (int j = 0; j < 4; ++j)
                    s[i][j] += q[i] * kk[j];
        }

        // apply the real masks (attention_mask AND padding_mask)
        int4 pv4 = *(const int4*)(pmk + b * LL + z0 + tc * 4);
        int pmv[4] = {pv4.x, pv4.y, pv4.z, pv4.w};
#pragma unroll
        for (int i = 0; i < 8; ++i) {
            int x = x0 + tr * 8 + i;
            int4 mv = *(const int4*)(am + ((size_t)b * LL + x) * LL + z0 + tc * 4);
            if (mv.x == 0 || pmv[0] == 0) s[i][0] = -1000000.0f;
            if (mv.y == 0 || pmv[1] == 0) s[i][1] = -1000000.0f;
            if (mv.z == 0 || pmv[2] == 0) s[i][2] = -1000000.0f;
            if (mv.w == 0 || pmv[3] == 0) s[i][3] = -1000000.0f;
        }

        // online softmax (row stats shared across the 16 lanes of a row group)
#pragma unroll
        for (int i = 0; i < 8; ++i) {
            float rm = fmaxf(fmaxf(s[i][0], s[i][1]), fmaxf(s[i][2], s[i][3]));
            rm = fmaxf(rm, __shfl_xor_sync(0xffffffffu, rm, 8));
            rm = fmaxf(rm, __shfl_xor_sync(0xffffffffu, rm, 4));
            rm = fmaxf(rm, __shfl_xor_sync(0xffffffffu, rm, 2));
            rm = fmaxf(rm, __shfl_xor_sync(0xffffffffu, rm, 1));
            float mn = fmaxf(m_i[i], rm);
            float corr = __expf(m_i[i] - mn);
            float p0 = __expf(s[i][0] - mn);
            float p1 = __expf(s[i][1] - mn);
            float p2 = __expf(s[i][2] - mn);
            float p3 = __expf(s[i][3] - mn);
            float ps = (p0 + p1) + (p2 + p3);
            ps += __shfl_xor_sync(0xffffffffu, ps, 8);
            ps += __shfl_xor_sync(0xffffffffu, ps, 4);
            ps += __shfl_xor_sync(0xffffffffu, ps, 2);
            ps += __shfl_xor_sync(0xffffffffu, ps, 1);
            l_i[i] = l_i[i] * corr + ps;
            m_i[i] = mn;
#pragma unroll
            for (int j = 0; j < 4; ++j) o[i][j] *= corr;
            float* prow = Ps + (tr * 8 + i) * QPAD + tc * 4;
            prow[0] = p0; prow[1] = p1; prow[2] = p2; prow[3] = p3;
        }
        __syncthreads();

        // O += P @ V
#pragma unroll 4
        for (int z = 0; z < FBN; ++z) {
            float pr[8], vv[4];
#pragma unroll
            for (int i = 0; i < 8; ++i) pr[i] = Ps[(tr * 8 + i) * QPAD + z];
#pragma unroll
            for (int j = 0; j < 4; ++j) vv[j] = Vs[z * QPAD + tc * 4 + j];
#pragma unroll
            for (int i = 0; i < 8; ++i)
#pragma unroll
                for (int j = 0; j < 4; ++j)
                    o[i][j] += pr[i] * vv[j];
        }
    }

    // epilogue: normalize and store into (b, l, h*d) layout
#pragma unroll
    for (int i = 0; i < 8; ++i) {
        float inv = 1.0f / l_i[i];
        int x = x0 + tr * 8 + i;
        float4 v;
        v.x = o[i][0] * inv;
        v.y = o[i][1] * inv;
        v.z = o[i][2] * inv;
        v.w = o[i][3] * inv;
        *(float4*)(Og + (size_t)(b * LL + x) * DMODEL + h * DD + tc * 4) = v;
    }
}

// ================================ launch ======================================
extern "C" void kernel_launch(void* const* d_in, const int* in_sizes, int n_in,
                              void* d_out, int out_size)
{
    const float* primary = (const float*)d_in[0];
    const float* context = (const float*)d_in[1];
    const int*   pmask   = (const int*)d_in[2];
    const int*   amask   = (const int*)d_in[3];
    const float* W_qs    = (const float*)d_in[4];
    const float* W_ks    = (const float*)d_in[5];
    const float* W_vs    = (const float*)d_in[6];
    const float* W_o     = (const float*)d_in[7];
    const float* b_o     = (const float*)d_in[8];
    float* out = (float*)d_out;

    float *Qp, *Kp, *Vp, *Ap;
    cudaGetSymbolAddress((void**)&Qp, g_Q);
    cudaGetSymbolAddress((void**)&Kp, g_K);
    cudaGetSymbolAddress((void**)&Vp, g_V);
    cudaGetSymbolAddress((void**)&Ap, g_A);

    dim3 gproj(DMODEL / GBN, MROWS / GBM);   // (8, 32)

    sgemm_kernel<false><<<gproj, 256>>>(primary, W_qs, Qp, nullptr, MROWS, DMODEL, DMODEL);
    sgemm_kernel<false><<<gproj, 256>>>(context, W_ks, Kp, nullptr, MROWS, DMODEL, DMODEL);
    sgemm_kernel<false><<<gproj, 256>>>(context, W_vs, Vp, nullptr, MROWS, DMODEL, DMODEL);

    size_t smbytes = (size_t)(FBM * QPAD + FBN * QPAD + FBN * QPAD + FBM * QPAD) * sizeof(float);
    cudaFuncSetAttribute(flash_kernel, cudaFuncAttributeMaxDynamicSharedMemorySize, (int)smbytes);
    flash_kernel<<<dim3(LL / FBM, HH, BB), 256, smbytes>>>(Qp, Kp, Vp, amask, pmask, Ap);

    sgemm_kernel<true><<<gproj, 256>>>(Ap, W_o, out, b_o, MROWS, DMODEL, DMODEL);
}

// round 3
// speedup vs baseline: 1.3607x; 1.3607x over previous
#include <cuda_runtime.h>
#include <cuda_bf16.h>
#include <math.h>
#include <stdint.h>

// Problem constants
#define BB 2
#define LL 2048
#define HH 16
#define DD 64
#define DMODEL 1024
#define MROWS (BB*LL)          // 4096

// ---------------- scratch (device globals: no allocations allowed) -------------
__device__ float g_Q[(size_t)MROWS * DMODEL];
__device__ float g_K[(size_t)MROWS * DMODEL];
__device__ float g_V[(size_t)MROWS * DMODEL];
__device__ float g_A[(size_t)MROWS * DMODEL];

// bf16 hi/lo splits
__device__ __align__(256) __nv_bfloat16 g_prim_hi[(size_t)MROWS * DMODEL];
__device__ __align__(256) __nv_bfloat16 g_prim_lo[(size_t)MROWS * DMODEL];
__device__ __align__(256) __nv_bfloat16 g_ctx_hi [(size_t)MROWS * DMODEL];
__device__ __align__(256) __nv_bfloat16 g_ctx_lo [(size_t)MROWS * DMODEL];
__device__ __align__(256) __nv_bfloat16 g_att_hi [(size_t)MROWS * DMODEL];
__device__ __align__(256) __nv_bfloat16 g_att_lo [(size_t)MROWS * DMODEL];
// transposed weights [N,K] K-major
__device__ __align__(256) __nv_bfloat16 g_WqT_hi[(size_t)DMODEL * DMODEL];
__device__ __align__(256) __nv_bfloat16 g_WqT_lo[(size_t)DMODEL * DMODEL];
__device__ __align__(256) __nv_bfloat16 g_WkT_hi[(size_t)DMODEL * DMODEL];
__device__ __align__(256) __nv_bfloat16 g_WkT_lo[(size_t)DMODEL * DMODEL];
__device__ __align__(256) __nv_bfloat16 g_WvT_hi[(size_t)DMODEL * DMODEL];
__device__ __align__(256) __nv_bfloat16 g_WvT_lo[(size_t)DMODEL * DMODEL];
__device__ __align__(256) __nv_bfloat16 g_WoT_hi[(size_t)DMODEL * DMODEL];
__device__ __align__(256) __nv_bfloat16 g_WoT_lo[(size_t)DMODEL * DMODEL];

// ============================== PTX helpers ===================================
__device__ __forceinline__ uint32_t smem_u32(const void* p) {
    uint32_t a;
    asm("{ .reg .u64 t; cvta.to.shared.u64 t, %1; cvt.u32.u64 %0, t; }" : "=r"(a) : "l"(p));
    return a;
}
__device__ __forceinline__ void cp_async16(uint32_t sdst, const void* gsrc) {
    asm volatile("cp.async.cg.shared.global [%0], [%1], 16;" :: "r"(sdst), "l"(gsrc));
}
#define CP_COMMIT() asm volatile("cp.async.commit_group;" ::: "memory")
#define CP_WAIT(n)  asm volatile("cp.async.wait_group %0;" :: "n"(n) : "memory")

__device__ __forceinline__ void ldm_x4(uint32_t* r, uint32_t addr) {
    asm volatile("ldmatrix.sync.aligned.m8n8.x4.shared.b16 {%0,%1,%2,%3}, [%4];"
        : "=r"(r[0]), "=r"(r[1]), "=r"(r[2]), "=r"(r[3]) : "r"(addr));
}
__device__ __forceinline__ void mma_bf16(float* c, const uint32_t* a, const uint32_t* b) {
    asm volatile("mma.sync.aligned.m16n8k16.row.col.f32.bf16.bf16.f32 "
        "{%0,%1,%2,%3}, {%4,%5,%6,%7}, {%8,%9}, {%0,%1,%2,%3};"
        : "+f"(c[0]), "+f"(c[1]), "+f"(c[2]), "+f"(c[3])
        : "r"(a[0]), "r"(a[1]), "r"(a[2]), "r"(a[3]), "r"(b[0]), "r"(b[1]));
}

// ====================== fp32 -> bf16 hi/lo split kernels ======================
__global__ __launch_bounds__(256)
void split_kernel(const float* __restrict__ x, __nv_bfloat16* __restrict__ hi,
                  __nv_bfloat16* __restrict__ lo, int n4)
{
    int i = blockIdx.x * blockDim.x + threadIdx.x;
    if (i >= n4) return;
    float4 v = *(const float4*)(x + (size_t)i * 4);
    __nv_bfloat16 h[4], l[4];
    float f[4] = {v.x, v.y, v.z, v.w};
#pragma unroll
    for (int j = 0; j < 4; ++j) {
        h[j] = __float2bfloat16(f[j]);
        l[j] = __float2bfloat16(f[j] - __bfloat162float(h[j]));
    }
    *(uint2*)(hi + (size_t)i * 4) = *(uint2*)h;
    *(uint2*)(lo + (size_t)i * 4) = *(uint2*)l;
}

// W[K,N] -> W^T[N,K] hi/lo
__global__ __launch_bounds__(256)
void split_T_kernel(const float* __restrict__ W, __nv_bfloat16* __restrict__ hiT,
                    __nv_bfloat16* __restrict__ loT, int K, int N)
{
    __shared__ float t[32][33];
    int k0 = blockIdx.y * 32, n0 = blockIdx.x * 32;
    int tx = threadIdx.x, ty = threadIdx.y;
#pragma unroll
    for (int j = 0; j < 4; ++j)
        t[ty + j * 8][tx] = W[(size_t)(k0 + ty + j * 8) * N + n0 + tx];
    __syncthreads();
#pragma unroll
    for (int j = 0; j < 4; ++j) {
        float v = t[tx][ty + j * 8];
        __nv_bfloat16 h = __float2bfloat16(v);
        __nv_bfloat16 l = __float2bfloat16(v - __bfloat162float(h));
        size_t off = (size_t)(n0 + ty + j * 8) * K + k0 + tx;
        hiT[off] = h;
        loT[off] = l;
    }
}

// ====================== mma.sync bf16-split GEMM ==============================
// C[M,N] = (Ahi+Alo)[M,K] @ (Bhi+Blo)^T, B stored [N,K] K-major.
// CTA 128x128, 8 warps (2x4), warp tile 64x32, BK=32, double-buffered cp.async.
#define GBK 32
#define TROW_B 80                 // padded row stride bytes (32 bf16 -> 64B data + 16B pad)
#define TILE_P (128 * TROW_B)     // 10240 B per tile
#define STAGE_P (4 * TILE_P)      // Ahi, Alo, Bhi, Blo

template <bool HAS_BIAS>
__global__ __launch_bounds__(256, 1)
void gemm_bf16s(const __nv_bfloat16* __restrict__ Ahi, const __nv_bfloat16* __restrict__ Alo,
                const __nv_bfloat16* __restrict__ Bhi, const __nv_bfloat16* __restrict__ Blo,
                float* __restrict__ C, const float* __restrict__ bias,
                int M, int N, int K)
{
    extern __shared__ char smem[];
    const uint32_t sb = smem_u32(smem);

    const int tid = threadIdx.x;
    const int wid = tid >> 5;
    const int lane = tid & 31;
    const int warp_m = wid >> 2;       // 0..1
    const int warp_n = wid & 3;        // 0..3
    const int bn = blockIdx.x * 128;
    const int bm = blockIdx.y * 128;

    const __nv_bfloat16* aHg = Ahi + (size_t)bm * K;
    const __nv_bfloat16* aLg = Alo + (size_t)bm * K;
    const __nv_bfloat16* bHg = Bhi + (size_t)bn * K;
    const __nv_bfloat16* bLg = Blo + (size_t)bn * K;

    // cp.async mapping: 512 16B lines per tile; each thread does 2 lines/tile.
    const int ldr0 = tid >> 2;          // row for t=0 (0..63)
    const int ldc0 = tid & 3;           // 16B chunk
    // t=1 covers rows 64..127

    float acc[4][4][4];
#pragma unroll
    for (int mt = 0; mt < 4; ++mt)
#pragma unroll
        for (int nt = 0; nt < 4; ++nt)
#pragma unroll
            for (int r = 0; r < 4; ++r) acc[mt][nt][r] = 0.0f;

    const int nch = K / GBK;

    // ldmatrix lane addresses (within a tile buffer)
    // A (x4, m16k16): lane -> row = (lane%8) + ((lane>>3)&1)*8, chunk = lane>>4
    const uint32_t a_row = (lane & 7) + ((lane >> 3) & 1) * 8;
    const uint32_t a_off = a_row * TROW_B + (lane >> 4) * 16;
    // B (x4 over n16k16): lane -> n = (lane%8) + (lane>>4)*8, chunk = (lane>>3)&1
    const uint32_t b_row = (lane & 7) + (lane >> 4) * 8;
    const uint32_t b_off = b_row * TROW_B + ((lane >> 3) & 1) * 16;

    auto load_chunk = [&](int stage, int k0) {
        uint32_t base = sb + stage * STAGE_P;
#pragma unroll
        for (int t = 0; t < 2; ++t) {
            int row = ldr0 + t * 64;
            uint32_t doff = (uint32_t)row * TROW_B + ldc0 * 16;
            size_t goff = (size_t)row * K + k0 + ldc0 * 8;
            cp_async16(base + 0 * TILE_P + doff, aHg + goff);
            cp_async16(base + 1 * TILE_P + doff, aLg + goff);
            cp_async16(base + 2 * TILE_P + doff, bHg + goff);
            cp_async16(base + 3 * TILE_P + doff, bLg + goff);
        }
        CP_COMMIT();
    };

    load_chunk(0, 0);

    for (int i = 0; i < nch; ++i) {
        if (i + 1 < nch) {
            load_chunk((i + 1) & 1, (i + 1) * GBK);
            CP_WAIT(1);
        } else {
            CP_WAIT(0);
        }
        __syncthreads();

        uint32_t base = sb + (i & 1) * STAGE_P;
        uint32_t aHb = base + 0 * TILE_P + warp_m * 64 * TROW_B + a_off;
        uint32_t aLb = base + 1 * TILE_P + warp_m * 64 * TROW_B + a_off;
        uint32_t bHb = base + 2 * TILE_P + warp_n * 32 * TROW_B + b_off;
        uint32_t bLb = base + 3 * TILE_P + warp_n * 32 * TROW_B + b_off;

#pragma unroll
        for (int ks = 0; ks < 2; ++ks) {
            uint32_t aH[4][4], aL[4][4], bH[2][4], bL[2][4];
#pragma unroll
            for (int mt = 0; mt < 4; ++mt) {
                ldm_x4(aH[mt], aHb + mt * 16 * TROW_B + ks * 32);
                ldm_x4(aL[mt], aLb + mt * 16 * TROW_B + ks * 32);
            }
#pragma unroll
            for (int n16 = 0; n16 < 2; ++n16) {
                ldm_x4(bH[n16], bHb + n16 * 16 * TROW_B + ks * 32);
                ldm_x4(bL[n16], bLb + n16 * 16 * TROW_B + ks * 32);
            }
#pragma unroll
            for (int mt = 0; mt < 4; ++mt)
#pragma unroll
                for (int nt = 0; nt < 4; ++nt) {
                    const uint32_t* bh = &bH[nt >> 1][(nt & 1) * 2];
                    const uint32_t* bl = &bL[nt >> 1][(nt & 1) * 2];
                    mma_bf16(acc[mt][nt], aH[mt], bh);
                    mma_bf16(acc[mt][nt], aH[mt], bl);
                    mma_bf16(acc[mt][nt], aL[mt], bh);
                }
        }
        __syncthreads();
    }

    // epilogue
    const int r0 = bm + warp_m * 64 + (lane >> 2);
    const int c0 = bn + warp_n * 32 + (lane & 3) * 2;
#pragma unroll
    for (int mt = 0; mt < 4; ++mt) {
#pragma unroll
        for (int nt = 0; nt < 4; ++nt) {
            int col = c0 + nt * 8;
            float bx = 0.f, by = 0.f;
            if (HAS_BIAS) { bx = bias[col]; by = bias[col + 1]; }
            float2 v0 = make_float2(acc[mt][nt][0] + bx, acc[mt][nt][1] + by);
            float2 v1 = make_float2(acc[mt][nt][2] + bx, acc[mt][nt][3] + by);
            *(float2*)(C + (size_t)(r0 + mt * 16) * N + col) = v0;
            *(float2*)(C + (size_t)(r0 + mt * 16 + 8) * N + col) = v1;
        }
    }
}

// ============================ Flash attention (fp32) ==========================
#define FBM 128
#define FBN 64
#define QPAD 65

__global__ __launch_bounds__(256)
void flash_kernel(const float* __restrict__ Qg, const float* __restrict__ Kg,
                  const float* __restrict__ Vg, const int* __restrict__ am,
                  const int* __restrict__ pmk, float* __restrict__ Og)
{
    extern __shared__ float sm[];
    float* Qs = sm;
    float* Ks = Qs + FBM * QPAD;
    float* Vs = Ks + FBN * QPAD;
    float* Ps = Vs + FBN * QPAD;

    const int tid = threadIdx.x;
    const int qb = (int)gridDim.x - 1 - (int)blockIdx.x;
    const int h = blockIdx.y;
    const int b = blockIdx.z;
    const int tr = tid >> 4;
    const int tc = tid & 15;

    const float scale = 0.125f;
    const int x0 = qb * FBM;

#pragma unroll
    for (int t = 0; t < 8; ++t) {
        int idx = tid + t * 256;
        int r = idx >> 4;
        int c4 = (idx & 15) << 2;
        float4 v = *(const float4*)(Qg + (size_t)(b * LL + x0 + r) * DMODEL + h * DD + c4);
        float* dst = Qs + r * QPAD + c4;
        dst[0] = v.x * scale; dst[1] = v.y * scale; dst[2] = v.z * scale; dst[3] = v.w * scale;
    }

    float m_i[8], l_i[8], o[8][4];
#pragma unroll
    for (int i = 0; i < 8; ++i) {
        m_i[i] = -3.0e38f; l_i[i] = 0.0f;
#pragma unroll
        for (int j = 0; j < 4; ++j) o[i][j] = 0.0f;
    }

    const int nkb = 2 * qb + 2;
    for (int kb = 0; kb < nkb; ++kb) {
        const int z0 = kb * FBN;
        __syncthreads();
#pragma unroll
        for (int t = 0; t < 4; ++t) {
            int idx = tid + t * 256;
            int r = idx >> 4;
            int c4 = (idx & 15) << 2;
            size_t goff = (size_t)(b * LL + z0 + r) * DMODEL + h * DD + c4;
            float4 kv = *(const float4*)(Kg + goff);
            float4 vv = *(const float4*)(Vg + goff);
            float* kd = Ks + r * QPAD + c4;
            float* vd = Vs + r * QPAD + c4;
            kd[0] = kv.x; kd[1] = kv.y; kd[2] = kv.z; kd[3] = kv.w;
            vd[0] = vv.x; vd[1] = vv.y; vd[2] = vv.z; vd[3] = vv.w;
        }
        __syncthreads();

        float s[8][4];
#pragma unroll
        for (int i = 0; i < 8; ++i)
#pragma unroll
            for (int j = 0; j < 4; ++j) s[i][j] = 0.0f;

#pragma unroll 4
        for (int d = 0; d < DD; ++d) {
            float q[8], kk[4];
#pragma unroll
            for (int i = 0; i < 8; ++i) q[i] = Qs[(tr * 8 + i) * QPAD + d];
#pragma unroll
            for (int j = 0; j < 4; ++j) kk[j] = Ks[(tc * 4 + j) * QPAD + d];
#pragma unroll
            for (int i = 0; i < 8; ++i)
#pragma unroll
                for (int j = 0; j < 4; ++j)
                    s[i][j] += q[i] * kk[j];
        }

        int4 pv4 = *(const int4*)(pmk + b * LL + z0 + tc * 4);
        int pmv[4] = {pv4.x, pv4.y, pv4.z, pv4.w};
#pragma unroll
        for (int i = 0; i < 8; ++i) {
            int x = x0 + tr * 8 + i;
            int4 mv = *(const int4*)(am + ((size_t)b * LL + x) * LL + z0 + tc * 4);
            if (mv.x == 0 || pmv[0] == 0) s[i][0] = -1000000.0f;
            if (mv.y == 0 || pmv[1] == 0) s[i][1] = -1000000.0f;
            if (mv.z == 0 || pmv[2] == 0) s[i][2] = -1000000.0f;
            if (mv.w == 0 || pmv[3] == 0) s[i][3] = -1000000.0f;
        }

#pragma unroll
        for (int i = 0; i < 8; ++i) {
            float rm = fmaxf(fmaxf(s[i][0], s[i][1]), fmaxf(s[i][2], s[i][3]));
            rm = fmaxf(rm, __shfl_xor_sync(0xffffffffu, rm, 8));
            rm = fmaxf(rm, __shfl_xor_sync(0xffffffffu, rm, 4));
            rm = fmaxf(rm, __shfl_xor_sync(0xffffffffu, rm, 2));
            rm = fmaxf(rm, __shfl_xor_sync(0xffffffffu, rm, 1));
            float mn = fmaxf(m_i[i], rm);
            float corr = __expf(m_i[i] - mn);
            float p0 = __expf(s[i][0] - mn);
            float p1 = __expf(s[i][1] - mn);
            float p2 = __expf(s[i][2] - mn);
            float p3 = __expf(s[i][3] - mn);
            float ps = (p0 + p1) + (p2 + p3);
            ps += __shfl_xor_sync(0xffffffffu, ps, 8);
            ps += __shfl_xor_sync(0xffffffffu, ps, 4);
            ps += __shfl_xor_sync(0xffffffffu, ps, 2);
            ps += __shfl_xor_sync(0xffffffffu, ps, 1);
            l_i[i] = l_i[i] * corr + ps;
            m_i[i] = mn;
#pragma unroll
            for (int j = 0; j < 4; ++j) o[i][j] *= corr;
            float* prow = Ps + (tr * 8 + i) * QPAD + tc * 4;
            prow[0] = p0; prow[1] = p1; prow[2] = p2; prow[3] = p3;
        }
        __syncthreads();

#pragma unroll 4
        for (int z = 0; z < FBN; ++z) {
            float pr[8], vv[4];
#pragma unroll
            for (int i = 0; i < 8; ++i) pr[i] = Ps[(tr * 8 + i) * QPAD + z];
#pragma unroll
            for (int j = 0; j < 4; ++j) vv[j] = Vs[z * QPAD + tc * 4 + j];
#pragma unroll
            for (int i = 0; i < 8; ++i)
#pragma unroll
                for (int j = 0; j < 4; ++j)
                    o[i][j] += pr[i] * vv[j];
        }
    }

#pragma unroll
    for (int i = 0; i < 8; ++i) {
        float inv = 1.0f / l_i[i];
        int x = x0 + tr * 8 + i;
        float4 v;
        v.x = o[i][0] * inv; v.y = o[i][1] * inv;
        v.z = o[i][2] * inv; v.w = o[i][3] * inv;
        *(float4*)(Og + (size_t)(b * LL + x) * DMODEL + h * DD + tc * 4) = v;
    }
}

// ================================ launch ======================================
extern "C" void kernel_launch(void* const* d_in, const int* in_sizes, int n_in,
                              void* d_out, int out_size)
{
    const float* primary = (const float*)d_in[0];
    const float* context = (const float*)d_in[1];
    const int*   pmask   = (const int*)d_in[2];
    const int*   amask   = (const int*)d_in[3];
    const float* W_qs    = (const float*)d_in[4];
    const float* W_ks    = (const float*)d_in[5];
    const float* W_vs    = (const float*)d_in[6];
    const float* W_o     = (const float*)d_in[7];
    const float* b_o     = (const float*)d_in[8];
    float* out = (float*)d_out;

    float *Qp, *Kp, *Vp, *Ap;
    cudaGetSymbolAddress((void**)&Qp, g_Q);
    cudaGetSymbolAddress((void**)&Kp, g_K);
    cudaGetSymbolAddress((void**)&Vp, g_V);
    cudaGetSymbolAddress((void**)&Ap, g_A);

    __nv_bfloat16 *pH, *pL, *cH, *cL, *aH, *aL;
    __nv_bfloat16 *qH, *qL, *kH, *kL, *vH, *vL, *oH, *oL;
    cudaGetSymbolAddress((void**)&pH, g_prim_hi); cudaGetSymbolAddress((void**)&pL, g_prim_lo);
    cudaGetSymbolAddress((void**)&cH, g_ctx_hi);  cudaGetSymbolAddress((void**)&cL, g_ctx_lo);
    cudaGetSymbolAddress((void**)&aH, g_att_hi);  cudaGetSymbolAddress((void**)&aL, g_att_lo);
    cudaGetSymbolAddress((void**)&qH, g_WqT_hi);  cudaGetSymbolAddress((void**)&qL, g_WqT_lo);
    cudaGetSymbolAddress((void**)&kH, g_WkT_hi);  cudaGetSymbolAddress((void**)&kL, g_WkT_lo);
    cudaGetSymbolAddress((void**)&vH, g_WvT_hi);  cudaGetSymbolAddress((void**)&vL, g_WvT_lo);
    cudaGetSymbolAddress((void**)&oH, g_WoT_hi);  cudaGetSymbolAddress((void**)&oL, g_WoT_lo);

    const int nact4 = (MROWS * DMODEL) / 4;
    split_kernel<<<nact4 / 256, 256>>>(primary, pH, pL, nact4);
    split_kernel<<<nact4 / 256, 256>>>(context, cH, cL, nact4);
    dim3 tb(32, 8), tg(DMODEL / 32, DMODEL / 32);
    split_T_kernel<<<tg, tb>>>(W_qs, qH, qL, DMODEL, DMODEL);
    split_T_kernel<<<tg, tb>>>(W_ks, kH, kL, DMODEL, DMODEL);
    split_T_kernel<<<tg, tb>>>(W_vs, vH, vL, DMODEL, DMODEL);
    split_T_kernel<<<tg, tb>>>(W_o,  oH, oL, DMODEL, DMODEL);

    size_t gsm = 2 * STAGE_P;   // 81920 B
    cudaFuncSetAttribute(gemm_bf16s<false>, cudaFuncAttributeMaxDynamicSharedMemorySize, (int)gsm);
    cudaFuncSetAttribute(gemm_bf16s<true>,  cudaFuncAttributeMaxDynamicSharedMemorySize, (int)gsm);
    dim3 gg(DMODEL / 128, MROWS / 128);   // (8, 32)

    gemm_bf16s<false><<<gg, 256, gsm>>>(pH, pL, qH, qL, Qp, nullptr, MROWS, DMODEL, DMODEL);
    gemm_bf16s<false><<<gg, 256, gsm>>>(cH, cL, kH, kL, Kp, nullptr, MROWS, DMODEL, DMODEL);
    gemm_bf16s<false><<<gg, 256, gsm>>>(cH, cL, vH, vL, Vp, nullptr, MROWS, DMODEL, DMODEL);

    size_t smbytes = (size_t)(FBM * QPAD + FBN * QPAD + FBN * QPAD + FBM * QPAD) * sizeof(float);
    cudaFuncSetAttribute(flash_kernel, cudaFuncAttributeMaxDynamicSharedMemorySize, (int)smbytes);
    flash_kernel<<<dim3(LL / FBM, HH, BB), 256, smbytes>>>(Qp, Kp, Vp, amask, pmask, Ap);

    split_kernel<<<nact4 / 256, 256>>>(Ap, aH, aL, nact4);
    gemm_bf16s<true><<<gg, 256, gsm>>>(aH, aL, oH, oL, out, b_o, MROWS, DMODEL, DMODEL);
}

// round 4
// speedup vs baseline: 2.4178x; 1.7769x over previous
#include <cuda_runtime.h>
#include <cuda_bf16.h>
#include <math.h>
#include <stdint.h>

// Problem constants
#define BB 2
#define LL 2048
#define HH 16
#define DD 64
#define DMODEL 1024
#define MROWS (BB*LL)          // 4096

// ---------------- scratch (device globals: no allocations allowed) -------------
// activations hi/lo
__device__ __align__(256) __nv_bfloat16 g_prim_hi[(size_t)MROWS * DMODEL];
__device__ __align__(256) __nv_bfloat16 g_prim_lo[(size_t)MROWS * DMODEL];
__device__ __align__(256) __nv_bfloat16 g_ctx_hi [(size_t)MROWS * DMODEL];
__device__ __align__(256) __nv_bfloat16 g_ctx_lo [(size_t)MROWS * DMODEL];
// Q/K/V projections hi/lo (written by GEMM epilogue)
__device__ __align__(256) __nv_bfloat16 g_Qhi[(size_t)MROWS * DMODEL];
__device__ __align__(256) __nv_bfloat16 g_Qlo[(size_t)MROWS * DMODEL];
__device__ __align__(256) __nv_bfloat16 g_Khi[(size_t)MROWS * DMODEL];
__device__ __align__(256) __nv_bfloat16 g_Klo[(size_t)MROWS * DMODEL];
__device__ __align__(256) __nv_bfloat16 g_Vhi[(size_t)MROWS * DMODEL];
__device__ __align__(256) __nv_bfloat16 g_Vlo[(size_t)MROWS * DMODEL];
// attention output hi/lo (written by flash epilogue)
__device__ __align__(256) __nv_bfloat16 g_att_hi[(size_t)MROWS * DMODEL];
__device__ __align__(256) __nv_bfloat16 g_att_lo[(size_t)MROWS * DMODEL];
// transposed weights [N,K] K-major hi/lo
__device__ __align__(256) __nv_bfloat16 g_WqT_hi[(size_t)DMODEL * DMODEL];
__device__ __align__(256) __nv_bfloat16 g_WqT_lo[(size_t)DMODEL * DMODEL];
__device__ __align__(256) __nv_bfloat16 g_WkT_hi[(size_t)DMODEL * DMODEL];
__device__ __align__(256) __nv_bfloat16 g_WkT_lo[(size_t)DMODEL * DMODEL];
__device__ __align__(256) __nv_bfloat16 g_WvT_hi[(size_t)DMODEL * DMODEL];
__device__ __align__(256) __nv_bfloat16 g_WvT_lo[(size_t)DMODEL * DMODEL];
__device__ __align__(256) __nv_bfloat16 g_WoT_hi[(size_t)DMODEL * DMODEL];
__device__ __align__(256) __nv_bfloat16 g_WoT_lo[(size_t)DMODEL * DMODEL];

// ============================== PTX helpers ===================================
__device__ __forceinline__ uint32_t smem_u32(const void* p) {
    uint32_t a;
    asm("{ .reg .u64 t; cvta.to.shared.u64 t, %1; cvt.u32.u64 %0, t; }" : "=r"(a) : "l"(p));
    return a;
}
__device__ __forceinline__ void cp_async16(uint32_t sdst, const void* gsrc) {
    asm volatile("cp.async.cg.shared.global [%0], [%1], 16;" :: "r"(sdst), "l"(gsrc));
}
#define CP_COMMIT() asm volatile("cp.async.commit_group;" ::: "memory")
#define CP_WAIT(n)  asm volatile("cp.async.wait_group %0;" :: "n"(n) : "memory")

__device__ __forceinline__ void ldm_x4(uint32_t* r, uint32_t addr) {
    asm volatile("ldmatrix.sync.aligned.m8n8.x4.shared.b16 {%0,%1,%2,%3}, [%4];"
        : "=r"(r[0]), "=r"(r[1]), "=r"(r[2]), "=r"(r[3]) : "r"(addr));
}
__device__ __forceinline__ void ldm_x4_t(uint32_t* r, uint32_t addr) {
    asm volatile("ldmatrix.sync.aligned.m8n8.x4.trans.shared.b16 {%0,%1,%2,%3}, [%4];"
        : "=r"(r[0]), "=r"(r[1]), "=r"(r[2]), "=r"(r[3]) : "r"(addr));
}
__device__ __forceinline__ void mma_bf16(float* c, const uint32_t* a, const uint32_t* b) {
    asm volatile("mma.sync.aligned.m16n8k16.row.col.f32.bf16.bf16.f32 "
        "{%0,%1,%2,%3}, {%4,%5,%6,%7}, {%8,%9}, {%0,%1,%2,%3};"
        : "+f"(c[0]), "+f"(c[1]), "+f"(c[2]), "+f"(c[3])
        : "r"(a[0]), "r"(a[1]), "r"(a[2]), "r"(a[3]), "r"(b[0]), "r"(b[1]));
}
// pack (p0,p1) -> bf16x2 hi (low half = p0), and residual lo pair
__device__ __forceinline__ void pack2(float p0, float p1, uint32_t& hi, uint32_t& lo) {
    asm("cvt.rn.bf16x2.f32 %0, %1, %2;" : "=r"(hi) : "f"(p1), "f"(p0));
    __nv_bfloat162 t = *reinterpret_cast<__nv_bfloat162*>(&hi);
    float r0 = p0 - __bfloat162float(t.x);
    float r1 = p1 - __bfloat162float(t.y);
    asm("cvt.rn.bf16x2.f32 %0, %1, %2;" : "=r"(lo) : "f"(r1), "f"(r0));
}

// ====================== fp32 -> bf16 hi/lo split kernels ======================
__global__ __launch_bounds__(256)
void split_kernel(const float* __restrict__ x, __nv_bfloat16* __restrict__ hi,
                  __nv_bfloat16* __restrict__ lo, int n4)
{
    int i = blockIdx.x * blockDim.x + threadIdx.x;
    if (i >= n4) return;
    float4 v = *(const float4*)(x + (size_t)i * 4);
    __nv_bfloat16 h[4], l[4];
    float f[4] = {v.x, v.y, v.z, v.w};
#pragma unroll
    for (int j = 0; j < 4; ++j) {
        h[j] = __float2bfloat16(f[j]);
        l[j] = __float2bfloat16(f[j] - __bfloat162float(h[j]));
    }
    *(uint2*)(hi + (size_t)i * 4) = *(uint2*)h;
    *(uint2*)(lo + (size_t)i * 4) = *(uint2*)l;
}

// W[K,N] -> W^T[N,K] hi/lo
__global__ __launch_bounds__(256)
void split_T_kernel(const float* __restrict__ W, __nv_bfloat16* __restrict__ hiT,
                    __nv_bfloat16* __restrict__ loT, int K, int N)
{
    __shared__ float t[32][33];
    int k0 = blockIdx.y * 32, n0 = blockIdx.x * 32;
    int tx = threadIdx.x, ty = threadIdx.y;
#pragma unroll
    for (int j = 0; j < 4; ++j)
        t[ty + j * 8][tx] = W[(size_t)(k0 + ty + j * 8) * N + n0 + tx];
    __syncthreads();
#pragma unroll
    for (int j = 0; j < 4; ++j) {
        float v = t[tx][ty + j * 8];
        __nv_bfloat16 h = __float2bfloat16(v);
        __nv_bfloat16 l = __float2bfloat16(v - __bfloat162float(h));
        size_t off = (size_t)(n0 + ty + j * 8) * K + k0 + tx;
        hiT[off] = h;
        loT[off] = l;
    }
}

// ====================== mma.sync bf16-split GEMM ==============================
// C = (Ahi+Alo)[M,K] @ (Bhi+Blo)^T, B stored [N,K] K-major.
// OM=0: fp32 C + bias.  OM=1: bf16 hi/lo output pair.
#define GBK 32
#define TROW_B 80
#define TILE_P (128 * TROW_B)
#define STAGE_P (4 * TILE_P)

template <int OM>
__global__ __launch_bounds__(256, 1)
void gemm_bf16s(const __nv_bfloat16* __restrict__ Ahi, const __nv_bfloat16* __restrict__ Alo,
                const __nv_bfloat16* __restrict__ Bhi, const __nv_bfloat16* __restrict__ Blo,
                float* __restrict__ C, __nv_bfloat16* __restrict__ Chi,
                __nv_bfloat16* __restrict__ Clo, const float* __restrict__ bias,
                int M, int N, int K)
{
    extern __shared__ char smem[];
    const uint32_t sb = smem_u32(smem);

    const int tid = threadIdx.x;
    const int wid = tid >> 5;
    const int lane = tid & 31;
    const int warp_m = wid >> 2;
    const int warp_n = wid & 3;
    const int bn = blockIdx.x * 128;
    const int bm = blockIdx.y * 128;

    const __nv_bfloat16* aHg = Ahi + (size_t)bm * K;
    const __nv_bfloat16* aLg = Alo + (size_t)bm * K;
    const __nv_bfloat16* bHg = Bhi + (size_t)bn * K;
    const __nv_bfloat16* bLg = Blo + (size_t)bn * K;

    const int ldr0 = tid >> 2;
    const int ldc0 = tid & 3;

    float acc[4][4][4];
#pragma unroll
    for (int mt = 0; mt < 4; ++mt)
#pragma unroll
        for (int nt = 0; nt < 4; ++nt)
#pragma unroll
            for (int r = 0; r < 4; ++r) acc[mt][nt][r] = 0.0f;

    const int nch = K / GBK;

    const uint32_t a_row = (lane & 7) + ((lane >> 3) & 1) * 8;
    const uint32_t a_off = a_row * TROW_B + (lane >> 4) * 16;
    const uint32_t b_row = (lane & 7) + (lane >> 4) * 8;
    const uint32_t b_off = b_row * TROW_B + ((lane >> 3) & 1) * 16;

    auto load_chunk = [&](int stage, int k0) {
        uint32_t base = sb + stage * STAGE_P;
#pragma unroll
        for (int t = 0; t < 2; ++t) {
            int row = ldr0 + t * 64;
            uint32_t doff = (uint32_t)row * TROW_B + ldc0 * 16;
            size_t goff = (size_t)row * K + k0 + ldc0 * 8;
            cp_async16(base + 0 * TILE_P + doff, aHg + goff);
            cp_async16(base + 1 * TILE_P + doff, aLg + goff);
            cp_async16(base + 2 * TILE_P + doff, bHg + goff);
            cp_async16(base + 3 * TILE_P + doff, bLg + goff);
        }
        CP_COMMIT();
    };

    load_chunk(0, 0);

    for (int i = 0; i < nch; ++i) {
        if (i + 1 < nch) {
            load_chunk((i + 1) & 1, (i + 1) * GBK);
            CP_WAIT(1);
        } else {
            CP_WAIT(0);
        }
        __syncthreads();

        uint32_t base = sb + (i & 1) * STAGE_P;
        uint32_t aHb = base + 0 * TILE_P + warp_m * 64 * TROW_B + a_off;
        uint32_t aLb = base + 1 * TILE_P + warp_m * 64 * TROW_B + a_off;
        uint32_t bHb = base + 2 * TILE_P + warp_n * 32 * TROW_B + b_off;
        uint32_t bLb = base + 3 * TILE_P + warp_n * 32 * TROW_B + b_off;

#pragma unroll
        for (int ks = 0; ks < 2; ++ks) {
            uint32_t aH[4][4], aL[4][4], bH[2][4], bL[2][4];
#pragma unroll
            for (int mt = 0; mt < 4; ++mt) {
                ldm_x4(aH[mt], aHb + mt * 16 * TROW_B + ks * 32);
                ldm_x4(aL[mt], aLb + mt * 16 * TROW_B + ks * 32);
            }
#pragma unroll
            for (int n16 = 0; n16 < 2; ++n16) {
                ldm_x4(bH[n16], bHb + n16 * 16 * TROW_B + ks * 32);
                ldm_x4(bL[n16], bLb + n16 * 16 * TROW_B + ks * 32);
            }
#pragma unroll
            for (int mt = 0; mt < 4; ++mt)
#pragma unroll
                for (int nt = 0; nt < 4; ++nt) {
                    const uint32_t* bh = &bH[nt >> 1][(nt & 1) * 2];
                    const uint32_t* bl = &bL[nt >> 1][(nt & 1) * 2];
                    mma_bf16(acc[mt][nt], aH[mt], bh);
                    mma_bf16(acc[mt][nt], aH[mt], bl);
                    mma_bf16(acc[mt][nt], aL[mt], bh);
                }
        }
        __syncthreads();
    }

    const int r0 = bm + warp_m * 64 + (lane >> 2);
    const int c0 = bn + warp_n * 32 + (lane & 3) * 2;
#pragma unroll
    for (int mt = 0; mt < 4; ++mt) {
#pragma unroll
        for (int nt = 0; nt < 4; ++nt) {
            int col = c0 + nt * 8;
            if (OM == 0) {
                float bx = bias[col], by = bias[col + 1];
                float2 v0 = make_float2(acc[mt][nt][0] + bx, acc[mt][nt][1] + by);
                float2 v1 = make_float2(acc[mt][nt][2] + bx, acc[mt][nt][3] + by);
                *(float2*)(C + (size_t)(r0 + mt * 16) * N + col) = v0;
                *(float2*)(C + (size_t)(r0 + mt * 16 + 8) * N + col) = v1;
            } else {
                uint32_t uh, ul;
                pack2(acc[mt][nt][0], acc[mt][nt][1], uh, ul);
                *(uint32_t*)(Chi + (size_t)(r0 + mt * 16) * N + col) = uh;
                *(uint32_t*)(Clo + (size_t)(r0 + mt * 16) * N + col) = ul;
                pack2(acc[mt][nt][2], acc[mt][nt][3], uh, ul);
                *(uint32_t*)(Chi + (size_t)(r0 + mt * 16 + 8) * N + col) = uh;
                *(uint32_t*)(Clo + (size_t)(r0 + mt * 16 + 8) * N + col) = ul;
            }
        }
    }
}

// ===================== Flash attention on mma.sync ============================
// CTA: 128 queries x one (b,h). 8 warps, each owns 16 query rows.
// S = Q@K^T (3 split MMAs), fp32 online softmax, P@V (3 split MMAs).
#define FROWB 144                  // smem row stride bytes (64 bf16 + pad)
#define FQ_LO_OFF 18432            // 128*144
#define FSTG_OFF 36864
#define FSTG_SZ 36864              // 4 arrays * 64*144
#define FK_HI 0
#define FK_LO 9216
#define FV_HI 18432
#define FV_LO 27648
#define FSMEM_TOTAL (FSTG_OFF + 2 * FSTG_SZ)   // 110592

__global__ __launch_bounds__(256, 1)
void flash_mma(const __nv_bfloat16* __restrict__ Qh, const __nv_bfloat16* __restrict__ Ql,
               const __nv_bfloat16* __restrict__ Kh, const __nv_bfloat16* __restrict__ Kl,
               const __nv_bfloat16* __restrict__ Vh, const __nv_bfloat16* __restrict__ Vl,
               const int* __restrict__ am, const int* __restrict__ pmk,
               __nv_bfloat16* __restrict__ Oh, __nv_bfloat16* __restrict__ Ol)
{
    extern __shared__ char smem[];
    const uint32_t sb = smem_u32(smem);
    const int tid = threadIdx.x, wid = tid >> 5, lane = tid & 31;
    const int qb = (int)gridDim.x - 1 - (int)blockIdx.x;
    const int h = blockIdx.y, b = blockIdx.z;
    const int x0 = qb * 128;

    // ---- Q tile load (both hi and lo), grouped with stage-0 commit ----
#pragma unroll
    for (int t = 0; t < 8; ++t) {
        int l = tid + t * 256;
        int arr = l >> 10, r = (l >> 3) & 127, c = l & 7;
        const __nv_bfloat16* src = arr ? Ql : Qh;
        cp_async16(sb + arr * FQ_LO_OFF + (uint32_t)r * FROWB + c * 16,
                   src + (size_t)(b * LL + x0 + r) * DMODEL + h * DD + c * 8);
    }
    auto load_kv = [&](int stg, int z0) {
        uint32_t base = sb + FSTG_OFF + (uint32_t)stg * FSTG_SZ;
#pragma unroll
        for (int t = 0; t < 8; ++t) {
            int l = tid + t * 256;
            int arr = l >> 9, r = (l >> 3) & 63, c = l & 7;
            const __nv_bfloat16* src = (arr & 2) ? ((arr & 1) ? Vl : Vh)
                                                 : ((arr & 1) ? Kl : Kh);
            cp_async16(base + (uint32_t)arr * 9216 + (uint32_t)r * FROWB + c * 16,
                       src + (size_t)(b * LL + z0 + r) * DMODEL + h * DD + c * 8);
        }
        CP_COMMIT();
    };
    load_kv(0, 0);   // commits Q + stage0 together

    // fragment lane offsets
    const uint32_t a_row = (lane & 7) + ((lane >> 3) & 1) * 8;
    const uint32_t a_base = (uint32_t)(wid * 16 + a_row) * FROWB + (lane >> 4) * 16;
    const uint32_t b_row = (lane & 7) + (lane >> 4) * 8;
    const uint32_t b_off = b_row * FROWB + ((lane >> 3) & 1) * 16;
    const int g2 = lane >> 3;
    const uint32_t v_off = (uint32_t)((g2 & 1) * 8 + (lane & 7)) * FROWB + (g2 >> 1) * 16;

    // mask pointers (int2 = 2 cols)
    const int xr = x0 + wid * 16 + (lane >> 2);
    const int2* am0 = (const int2*)am + (size_t)(b * LL + xr) * (LL / 2);
    const int2* am1 = am0 + (size_t)8 * (LL / 2);
    const int2* pm2 = (const int2*)pmk + (size_t)b * (LL / 2);

    float m_s[2] = {-3.0e38f, -3.0e38f};
    float l_s[2] = {0.0f, 0.0f};
    float o[8][4];
#pragma unroll
    for (int nt = 0; nt < 8; ++nt)
#pragma unroll
        for (int r = 0; r < 4; ++r) o[nt][r] = 0.0f;

    const float SC = 0.125f;
    const float NEG = -1000000.0f;
    const int nkb = 2 * qb + 2;

    for (int kb = 0; kb < nkb; ++kb) {
        if (kb + 1 < nkb) {
            load_kv((kb + 1) & 1, (kb + 1) * 64);
            CP_WAIT(1);
        } else {
            CP_WAIT(0);
        }
        __syncthreads();

        const uint32_t kvb = sb + FSTG_OFF + (uint32_t)(kb & 1) * FSTG_SZ;

        // ---- S = Q @ K^T ----
        float s[8][4];
#pragma unroll
        for (int nt = 0; nt < 8; ++nt)
#pragma unroll
            for (int r = 0; r < 4; ++r) s[nt][r] = 0.0f;

#pragma unroll
        for (int kt = 0; kt < 4; ++kt) {
            uint32_t qh[4], ql[4];
            ldm_x4(qh, sb + a_base + kt * 32);
            ldm_x4(ql, sb + FQ_LO_OFF + a_base + kt * 32);
            uint32_t khf[4][4], klf[4][4];
#pragma unroll
            for (int g = 0; g < 4; ++g) {
                uint32_t ko = kvb + (uint32_t)g * (16 * FROWB) + b_off + kt * 32;
                ldm_x4(khf[g], ko + FK_HI);
                ldm_x4(klf[g], ko + FK_LO);
            }
#pragma unroll
            for (int nt = 0; nt < 8; ++nt) {
                const uint32_t* bh = &khf[nt >> 1][(nt & 1) * 2];
                const uint32_t* bl = &klf[nt >> 1][(nt & 1) * 2];
                mma_bf16(s[nt], qh, bh);
                mma_bf16(s[nt], qh, bl);
                mma_bf16(s[nt], ql, bh);
            }
        }

        // ---- scale + masks (real inputs) ----
        const int z0 = kb * 64;
        const int ci = (z0 >> 1) + (lane & 3);
#pragma unroll
        for (int nt = 0; nt < 8; ++nt) {
            int2 pm = pm2[ci + nt * 4];
            int2 u0 = am0[ci + nt * 4];
            int2 u1 = am1[ci + nt * 4];
            s[nt][0] = (u0.x != 0 && pm.x != 0) ? s[nt][0] * SC : NEG;
            s[nt][1] = (u0.y != 0 && pm.y != 0) ? s[nt][1] * SC : NEG;
            s[nt][2] = (u1.x != 0 && pm.x != 0) ? s[nt][2] * SC : NEG;
            s[nt][3] = (u1.y != 0 && pm.y != 0) ? s[nt][3] * SC : NEG;
        }

        // ---- online softmax (rows r and r+8 per thread) ----
#pragma unroll
        for (int j = 0; j < 2; ++j) {
            const int j2 = j * 2;
            float rm = NEG;
#pragma unroll
            for (int nt = 0; nt < 8; ++nt)
                rm = fmaxf(rm, fmaxf(s[nt][j2], s[nt][j2 + 1]));
            rm = fmaxf(rm, __shfl_xor_sync(0xffffffffu, rm, 1));
            rm = fmaxf(rm, __shfl_xor_sync(0xffffffffu, rm, 2));
            float mn = fmaxf(m_s[j], rm);
            float corr = __expf(m_s[j] - mn);
            float ps = 0.0f;
#pragma unroll
            for (int nt = 0; nt < 8; ++nt) {
                float p0 = __expf(s[nt][j2] - mn);
                float p1 = __expf(s[nt][j2 + 1] - mn);
                s[nt][j2] = p0; s[nt][j2 + 1] = p1;
                ps += p0 + p1;
            }
            ps += __shfl_xor_sync(0xffffffffu, ps, 1);
            ps += __shfl_xor_sync(0xffffffffu, ps, 2);
            l_s[j] = l_s[j] * corr + ps;
            m_s[j] = mn;
#pragma unroll
            for (int nt = 0; nt < 8; ++nt) {
                o[nt][j2] *= corr;
                o[nt][j2 + 1] *= corr;
            }
        }

        // ---- O += P @ V ----
#pragma unroll
        for (int kt = 0; kt < 4; ++kt) {
            uint32_t ah[4], al[4];
            pack2(s[2 * kt][0], s[2 * kt][1], ah[0], al[0]);
            pack2(s[2 * kt][2], s[2 * kt][3], ah[1], al[1]);
            pack2(s[2 * kt + 1][0], s[2 * kt + 1][1], ah[2], al[2]);
            pack2(s[2 * kt + 1][2], s[2 * kt + 1][3], ah[3], al[3]);

            uint32_t vhf[4][4], vlf[4][4];
#pragma unroll
            for (int g = 0; g < 4; ++g) {
                uint32_t vo = kvb + (uint32_t)kt * (16 * FROWB) + (uint32_t)g * 32 + v_off;
                ldm_x4_t(vhf[g], vo + FV_HI);
                ldm_x4_t(vlf[g], vo + FV_LO);
            }
#pragma unroll
            for (int nt = 0; nt < 8; ++nt) {
                const uint32_t* bh = &vhf[nt >> 1][(nt & 1) * 2];
                const uint32_t* bl = &vlf[nt >> 1][(nt & 1) * 2];
                mma_bf16(o[nt], ah, bh);
                mma_bf16(o[nt], ah, bl);
                mma_bf16(o[nt], al, bh);
            }
        }
        __syncthreads();
    }

    // ---- epilogue: normalize, split hi/lo, store ----
#pragma unroll
    for (int j = 0; j < 2; ++j) {
        float inv = 1.0f / l_s[j];
        size_t rowoff = (size_t)(b * LL + xr + j * 8) * DMODEL + h * DD + (lane & 3) * 2;
#pragma unroll
        for (int nt = 0; nt < 8; ++nt) {
            float c0 = o[nt][j * 2] * inv;
            float c1 = o[nt][j * 2 + 1] * inv;
            uint32_t uh, ul;
            pack2(c0, c1, uh, ul);
            *(uint32_t*)(Oh + rowoff + nt * 8) = uh;
            *(uint32_t*)(Ol + rowoff + nt * 8) = ul;
        }
    }
}

// ================================ launch ======================================
extern "C" void kernel_launch(void* const* d_in, const int* in_sizes, int n_in,
                              void* d_out, int out_size)
{
    const float* primary = (const float*)d_in[0];
    const float* context = (const float*)d_in[1];
    const int*   pmask   = (const int*)d_in[2];
    const int*   amask   = (const int*)d_in[3];
    const float* W_qs    = (const float*)d_in[4];
    const float* W_ks    = (const float*)d_in[5];
    const float* W_vs    = (const float*)d_in[6];
    const float* W_o     = (const float*)d_in[7];
    const float* b_o     = (const float*)d_in[8];
    float* out = (float*)d_out;

    __nv_bfloat16 *pH, *pL, *cH, *cL, *aH, *aL;
    __nv_bfloat16 *QH, *QL, *KH, *KL, *VH, *VL;
    __nv_bfloat16 *qH, *qL, *kH, *kL, *vH, *vL, *oH, *oL;
    cudaGetSymbolAddress((void**)&pH, g_prim_hi); cudaGetSymbolAddress((void**)&pL, g_prim_lo);
    cudaGetSymbolAddress((void**)&cH, g_ctx_hi);  cudaGetSymbolAddress((void**)&cL, g_ctx_lo);
    cudaGetSymbolAddress((void**)&aH, g_att_hi);  cudaGetSymbolAddress((void**)&aL, g_att_lo);
    cudaGetSymbolAddress((void**)&QH, g_Qhi);     cudaGetSymbolAddress((void**)&QL, g_Qlo);
    cudaGetSymbolAddress((void**)&KH, g_Khi);     cudaGetSymbolAddress((void**)&KL, g_Klo);
    cudaGetSymbolAddress((void**)&VH, g_Vhi);     cudaGetSymbolAddress((void**)&VL, g_Vlo);
    cudaGetSymbolAddress((void**)&qH, g_WqT_hi);  cudaGetSymbolAddress((void**)&qL, g_WqT_lo);
    cudaGetSymbolAddress((void**)&kH, g_WkT_hi);  cudaGetSymbolAddress((void**)&kL, g_WkT_lo);
    cudaGetSymbolAddress((void**)&vH, g_WvT_hi);  cudaGetSymbolAddress((void**)&vL, g_WvT_lo);
    cudaGetSymbolAddress((void**)&oH, g_WoT_hi);  cudaGetSymbolAddress((void**)&oL, g_WoT_lo);

    const int nact4 = (MROWS * DMODEL) / 4;
    split_kernel<<<nact4 / 256, 256>>>(primary, pH, pL, nact4);
    split_kernel<<<nact4 / 256, 256>>>(context, cH, cL, nact4);
    dim3 tb(32, 8), tg(DMODEL / 32, DMODEL / 32);
    split_T_kernel<<<tg, tb>>>(W_qs, qH, qL, DMODEL, DMODEL);
    split_T_kernel<<<tg, tb>>>(W_ks, kH, kL, DMODEL, DMODEL);
    split_T_kernel<<<tg, tb>>>(W_vs, vH, vL, DMODEL, DMODEL);
    split_T_kernel<<<tg, tb>>>(W_o,  oH, oL, DMODEL, DMODEL);

    size_t gsm = 2 * STAGE_P;
    cudaFuncSetAttribute(gemm_bf16s<0>, cudaFuncAttributeMaxDynamicSharedMemorySize, (int)gsm);
    cudaFuncSetAttribute(gemm_bf16s<1>, cudaFuncAttributeMaxDynamicSharedMemorySize, (int)gsm);
    dim3 gg(DMODEL / 128, MROWS / 128);

    gemm_bf16s<1><<<gg, 256, gsm>>>(pH, pL, qH, qL, nullptr, QH, QL, nullptr, MROWS, DMODEL, DMODEL);
    gemm_bf16s<1><<<gg, 256, gsm>>>(cH, cL, kH, kL, nullptr, KH, KL, nullptr, MROWS, DMODEL, DMODEL);
    gemm_bf16s<1><<<gg, 256, gsm>>>(cH, cL, vH, vL, nullptr, VH, VL, nullptr, MROWS, DMODEL, DMODEL);

    cudaFuncSetAttribute(flash_mma, cudaFuncAttributeMaxDynamicSharedMemorySize, FSMEM_TOTAL);
    flash_mma<<<dim3(LL / 128, HH, BB), 256, FSMEM_TOTAL>>>(QH, QL, KH, KL, VH, VL,
                                                            amask, pmask, aH, aL);

    gemm_bf16s<0><<<gg, 256, gsm>>>(aH, aL, oH, oL, out, nullptr, nullptr, b_o, MROWS, DMODEL, DMODEL);
}

// round 5
// speedup vs baseline: 2.4761x; 1.0241x over previous
#include <cuda_runtime.h>
#include <cuda_bf16.h>
#include <math.h>
#include <stdint.h>

// Problem constants
#define BB 2
#define LL 2048
#define HH 16
#define DD 64
#define DMODEL 1024
#define MROWS (BB*LL)          // 4096

// ---------------- scratch (device globals: no allocations allowed) -------------
__device__ __align__(256) __nv_bfloat16 g_prim_hi[(size_t)MROWS * DMODEL];
__device__ __align__(256) __nv_bfloat16 g_prim_lo[(size_t)MROWS * DMODEL];
__device__ __align__(256) __nv_bfloat16 g_ctx_hi [(size_t)MROWS * DMODEL];
__device__ __align__(256) __nv_bfloat16 g_ctx_lo [(size_t)MROWS * DMODEL];
__device__ __align__(256) __nv_bfloat16 g_Qhi[(size_t)MROWS * DMODEL];
__device__ __align__(256) __nv_bfloat16 g_Qlo[(size_t)MROWS * DMODEL];
__device__ __align__(256) __nv_bfloat16 g_Khi[(size_t)MROWS * DMODEL];
__device__ __align__(256) __nv_bfloat16 g_Klo[(size_t)MROWS * DMODEL];
__device__ __align__(256) __nv_bfloat16 g_Vhi[(size_t)MROWS * DMODEL];
__device__ __align__(256) __nv_bfloat16 g_Vlo[(size_t)MROWS * DMODEL];
__device__ __align__(256) __nv_bfloat16 g_att_hi[(size_t)MROWS * DMODEL];
__device__ __align__(256) __nv_bfloat16 g_att_lo[(size_t)MROWS * DMODEL];
__device__ __align__(256) __nv_bfloat16 g_WqT_hi[(size_t)DMODEL * DMODEL];
__device__ __align__(256) __nv_bfloat16 g_WqT_lo[(size_t)DMODEL * DMODEL];
__device__ __align__(256) __nv_bfloat16 g_WkT_hi[(size_t)DMODEL * DMODEL];
__device__ __align__(256) __nv_bfloat16 g_WkT_lo[(size_t)DMODEL * DMODEL];
__device__ __align__(256) __nv_bfloat16 g_WvT_hi[(size_t)DMODEL * DMODEL];
__device__ __align__(256) __nv_bfloat16 g_WvT_lo[(size_t)DMODEL * DMODEL];
__device__ __align__(256) __nv_bfloat16 g_WoT_hi[(size_t)DMODEL * DMODEL];
__device__ __align__(256) __nv_bfloat16 g_WoT_lo[(size_t)DMODEL * DMODEL];

// ============================== PTX helpers ===================================
__device__ __forceinline__ uint32_t smem_u32(const void* p) {
    uint32_t a;
    asm("{ .reg .u64 t; cvta.to.shared.u64 t, %1; cvt.u32.u64 %0, t; }" : "=r"(a) : "l"(p));
    return a;
}
__device__ __forceinline__ void cp_async16(uint32_t sdst, const void* gsrc) {
    asm volatile("cp.async.cg.shared.global [%0], [%1], 16;" :: "r"(sdst), "l"(gsrc));
}
#define CP_COMMIT() asm volatile("cp.async.commit_group;" ::: "memory")
#define CP_WAIT(n)  asm volatile("cp.async.wait_group %0;" :: "n"(n) : "memory")

__device__ __forceinline__ void ldm_x4(uint32_t* r, uint32_t addr) {
    asm volatile("ldmatrix.sync.aligned.m8n8.x4.shared.b16 {%0,%1,%2,%3}, [%4];"
        : "=r"(r[0]), "=r"(r[1]), "=r"(r[2]), "=r"(r[3]) : "r"(addr));
}
__device__ __forceinline__ void ldm_x4_t(uint32_t* r, uint32_t addr) {
    asm volatile("ldmatrix.sync.aligned.m8n8.x4.trans.shared.b16 {%0,%1,%2,%3}, [%4];"
        : "=r"(r[0]), "=r"(r[1]), "=r"(r[2]), "=r"(r[3]) : "r"(addr));
}
__device__ __forceinline__ void mma_bf16(float* c, const uint32_t* a, const uint32_t* b) {
    asm volatile("mma.sync.aligned.m16n8k16.row.col.f32.bf16.bf16.f32 "
        "{%0,%1,%2,%3}, {%4,%5,%6,%7}, {%8,%9}, {%0,%1,%2,%3};"
        : "+f"(c[0]), "+f"(c[1]), "+f"(c[2]), "+f"(c[3])
        : "r"(a[0]), "r"(a[1]), "r"(a[2]), "r"(a[3]), "r"(b[0]), "r"(b[1]));
}
__device__ __forceinline__ void pack2(float p0, float p1, uint32_t& hi, uint32_t& lo) {
    asm("cvt.rn.bf16x2.f32 %0, %1, %2;" : "=r"(hi) : "f"(p1), "f"(p0));
    __nv_bfloat162 t = *reinterpret_cast<__nv_bfloat162*>(&hi);
    float r0 = p0 - __bfloat162float(t.x);
    float r1 = p1 - __bfloat162float(t.y);
    asm("cvt.rn.bf16x2.f32 %0, %1, %2;" : "=r"(lo) : "f"(r1), "f"(r0));
}

// ====================== fp32 -> bf16 hi/lo split kernels ======================
__global__ __launch_bounds__(256)
void split_kernel(const float* __restrict__ x, __nv_bfloat16* __restrict__ hi,
                  __nv_bfloat16* __restrict__ lo, int n4)
{
    int i = blockIdx.x * blockDim.x + threadIdx.x;
    if (i >= n4) return;
    float4 v = *(const float4*)(x + (size_t)i * 4);
    __nv_bfloat16 h[4], l[4];
    float f[4] = {v.x, v.y, v.z, v.w};
#pragma unroll
    for (int j = 0; j < 4; ++j) {
        h[j] = __float2bfloat16(f[j]);
        l[j] = __float2bfloat16(f[j] - __bfloat162float(h[j]));
    }
    *(uint2*)(hi + (size_t)i * 4) = *(uint2*)h;
    *(uint2*)(lo + (size_t)i * 4) = *(uint2*)l;
}

__global__ __launch_bounds__(256)
void split_T_kernel(const float* __restrict__ W, __nv_bfloat16* __restrict__ hiT,
                    __nv_bfloat16* __restrict__ loT, int K, int N)
{
    __shared__ float t[32][33];
    int k0 = blockIdx.y * 32, n0 = blockIdx.x * 32;
    int tx = threadIdx.x, ty = threadIdx.y;
#pragma unroll
    for (int j = 0; j < 4; ++j)
        t[ty + j * 8][tx] = W[(size_t)(k0 + ty + j * 8) * N + n0 + tx];
    __syncthreads();
#pragma unroll
    for (int j = 0; j < 4; ++j) {
        float v = t[tx][ty + j * 8];
        __nv_bfloat16 h = __float2bfloat16(v);
        __nv_bfloat16 l = __float2bfloat16(v - __bfloat162float(h));
        size_t off = (size_t)(n0 + ty + j * 8) * K + k0 + tx;
        hiT[off] = h;
        loT[off] = l;
    }
}

// ====================== mma.sync bf16-split GEMM ==============================
// CTA 256x128, 512 threads (16 warps 4x4, warp tile 64x32), BK=32, double buffer.
#define GBK 32
#define TROW_B 80
#define OFF_AH 0
#define OFF_AL 20480               // 256*80
#define OFF_BH 40960
#define OFF_BL 51200               // +128*80
#define STAGE_P 61440

template <int OM>
__global__ __launch_bounds__(512, 1)
void gemm_bf16s(const __nv_bfloat16* __restrict__ Ahi, const __nv_bfloat16* __restrict__ Alo,
                const __nv_bfloat16* __restrict__ Bhi, const __nv_bfloat16* __restrict__ Blo,
                float* __restrict__ C, __nv_bfloat16* __restrict__ Chi,
                __nv_bfloat16* __restrict__ Clo, const float* __restrict__ bias,
                int M, int N, int K)
{
    extern __shared__ char smem[];
    const uint32_t sb = smem_u32(smem);

    const int tid = threadIdx.x;
    const int wid = tid >> 5;
    const int lane = tid & 31;
    const int warp_m = wid >> 2;       // 0..3
    const int warp_n = wid & 3;        // 0..3
    const int bn = blockIdx.x * 128;
    const int bm = blockIdx.y * 256;

    const __nv_bfloat16* aHg = Ahi + (size_t)bm * K;
    const __nv_bfloat16* aLg = Alo + (size_t)bm * K;
    const __nv_bfloat16* bHg = Bhi + (size_t)bn * K;
    const __nv_bfloat16* bLg = Blo + (size_t)bn * K;

    float acc[4][4][4];
#pragma unroll
    for (int mt = 0; mt < 4; ++mt)
#pragma unroll
        for (int nt = 0; nt < 4; ++nt)
#pragma unroll
            for (int r = 0; r < 4; ++r) acc[mt][nt][r] = 0.0f;

    const int nch = K / GBK;

    const uint32_t a_row = (lane & 7) + ((lane >> 3) & 1) * 8;
    const uint32_t a_off = a_row * TROW_B + (lane >> 4) * 16;
    const uint32_t b_row = (lane & 7) + (lane >> 4) * 8;
    const uint32_t b_off = b_row * TROW_B + ((lane >> 3) & 1) * 16;

    auto load_chunk = [&](int stage, int k0) {
        uint32_t base = sb + (uint32_t)stage * STAGE_P;
        // A: 1024 16B lines per array, 2 lines/thread
#pragma unroll
        for (int t = 0; t < 2; ++t) {
            int l = tid * 2 + t;
            int row = l >> 2, cb = l & 3;
            uint32_t doff = (uint32_t)row * TROW_B + cb * 16;
            size_t goff = (size_t)row * K + k0 + cb * 8;
            cp_async16(base + OFF_AH + doff, aHg + goff);
            cp_async16(base + OFF_AL + doff, aLg + goff);
        }
        // B: 512 lines per array, 1 line/thread
        {
            int row = tid >> 2, cb = tid & 3;
            uint32_t doff = (uint32_t)row * TROW_B + cb * 16;
            size_t goff = (size_t)row * K + k0 + cb * 8;
            cp_async16(base + OFF_BH + doff, bHg + goff);
            cp_async16(base + OFF_BL + doff, bLg + goff);
        }
        CP_COMMIT();
    };

    load_chunk(0, 0);

    for (int i = 0; i < nch; ++i) {
        if (i + 1 < nch) {
            load_chunk((i + 1) & 1, (i + 1) * GBK);
            CP_WAIT(1);
        } else {
            CP_WAIT(0);
        }
        __syncthreads();

        uint32_t base = sb + (uint32_t)(i & 1) * STAGE_P;
        uint32_t aHb = base + OFF_AH + warp_m * 64 * TROW_B + a_off;
        uint32_t aLb = base + OFF_AL + warp_m * 64 * TROW_B + a_off;
        uint32_t bHb = base + OFF_BH + warp_n * 32 * TROW_B + b_off;
        uint32_t bLb = base + OFF_BL + warp_n * 32 * TROW_B + b_off;

#pragma unroll
        for (int ks = 0; ks < 2; ++ks) {
            uint32_t aH[4][4], aL[4][4], bH[2][4], bL[2][4];
#pragma unroll
            for (int mt = 0; mt < 4; ++mt) {
                ldm_x4(aH[mt], aHb + mt * 16 * TROW_B + ks * 32);
                ldm_x4(aL[mt], aLb + mt * 16 * TROW_B + ks * 32);
            }
#pragma unroll
            for (int n16 = 0; n16 < 2; ++n16) {
                ldm_x4(bH[n16], bHb + n16 * 16 * TROW_B + ks * 32);
                ldm_x4(bL[n16], bLb + n16 * 16 * TROW_B + ks * 32);
            }
#pragma unroll
            for (int mt = 0; mt < 4; ++mt)
#pragma unroll
                for (int nt = 0; nt < 4; ++nt) {
                    const uint32_t* bh = &bH[nt >> 1][(nt & 1) * 2];
                    const uint32_t* bl = &bL[nt >> 1][(nt & 1) * 2];
                    mma_bf16(acc[mt][nt], aH[mt], bh);
                    mma_bf16(acc[mt][nt], aH[mt], bl);
                    mma_bf16(acc[mt][nt], aL[mt], bh);
                }
        }
        __syncthreads();
    }

    const int r0 = bm + warp_m * 64 + (lane >> 2);
    const int c0 = bn + warp_n * 32 + (lane & 3) * 2;
#pragma unroll
    for (int mt = 0; mt < 4; ++mt) {
#pragma unroll
        for (int nt = 0; nt < 4; ++nt) {
            int col = c0 + nt * 8;
            if (OM == 0) {
                float bx = bias[col], by = bias[col + 1];
                float2 v0 = make_float2(acc[mt][nt][0] + bx, acc[mt][nt][1] + by);
                float2 v1 = make_float2(acc[mt][nt][2] + bx, acc[mt][nt][3] + by);
                *(float2*)(C + (size_t)(r0 + mt * 16) * N + col) = v0;
                *(float2*)(C + (size_t)(r0 + mt * 16 + 8) * N + col) = v1;
            } else {
                uint32_t uh, ul;
                pack2(acc[mt][nt][0], acc[mt][nt][1], uh, ul);
                *(uint32_t*)(Chi + (size_t)(r0 + mt * 16) * N + col) = uh;
                *(uint32_t*)(Clo + (size_t)(r0 + mt * 16) * N + col) = ul;
                pack2(acc[mt][nt][2], acc[mt][nt][3], uh, ul);
                *(uint32_t*)(Chi + (size_t)(r0 + mt * 16 + 8) * N + col) = uh;
                *(uint32_t*)(Clo + (size_t)(r0 + mt * 16 + 8) * N + col) = ul;
            }
        }
    }
}

// ===================== Flash attention on mma.sync ============================
// CTA: 256 queries x one (b,h), 512 threads (16 warps x 16 rows).
// Masks are only read for the <=4 diagonal blocks (interior blocks are fully
// below the causal diagonal given the loop bound already assumes tril).
#define FROWB 144
#define FQ_HI 0
#define FQ_LO 36864                // 256*144
#define FSTG_OFF 73728
#define FSTG_SZ 36864              // 4 arrays * 64*144
#define FK_HI 0
#define FK_LO 9216
#define FV_HI 18432
#define FV_LO 27648
#define FSMEM_TOTAL (FSTG_OFF + 2 * FSTG_SZ)   // 147456

__global__ __launch_bounds__(512, 1)
void flash_mma(const __nv_bfloat16* __restrict__ Qh, const __nv_bfloat16* __restrict__ Ql,
               const __nv_bfloat16* __restrict__ Kh, const __nv_bfloat16* __restrict__ Kl,
               const __nv_bfloat16* __restrict__ Vh, const __nv_bfloat16* __restrict__ Vl,
               const int* __restrict__ am, const int* __restrict__ pmk,
               __nv_bfloat16* __restrict__ Oh, __nv_bfloat16* __restrict__ Ol)
{
    extern __shared__ char smem[];
    const uint32_t sb = smem_u32(smem);
    const int tid = threadIdx.x, wid = tid >> 5, lane = tid & 31;
    const int qb = (int)gridDim.x - 1 - (int)blockIdx.x;
    const int h = blockIdx.y, b = blockIdx.z;
    const int x0 = qb * 256;

    // Q tile hi+lo: 4096 lines, 8 per thread
#pragma unroll
    for (int t = 0; t < 8; ++t) {
        int l = tid + t * 512;
        int arr = l >> 11, r = (l >> 3) & 255, c = l & 7;
        const __nv_bfloat16* src = arr ? Ql : Qh;
        cp_async16(sb + (arr ? FQ_LO : FQ_HI) + (uint32_t)r * FROWB + c * 16,
                   src + (size_t)(b * LL + x0 + r) * DMODEL + h * DD + c * 8);
    }
    auto load_kv = [&](int stg, int z0) {
        uint32_t base = sb + FSTG_OFF + (uint32_t)stg * FSTG_SZ;
#pragma unroll
        for (int t = 0; t < 4; ++t) {
            int l = tid + t * 512;
            int arr = l >> 9, r = (l >> 3) & 63, c = l & 7;
            const __nv_bfloat16* src = (arr & 2) ? ((arr & 1) ? Vl : Vh)
                                                 : ((arr & 1) ? Kl : Kh);
            cp_async16(base + (uint32_t)arr * 9216 + (uint32_t)r * FROWB + c * 16,
                       src + (size_t)(b * LL + z0 + r) * DMODEL + h * DD + c * 8);
        }
        CP_COMMIT();
    };
    load_kv(0, 0);

    const uint32_t a_row = (lane & 7) + ((lane >> 3) & 1) * 8;
    const uint32_t a_base = (uint32_t)(wid * 16 + a_row) * FROWB + (lane >> 4) * 16;
    const uint32_t b_row = (lane & 7) + (lane >> 4) * 8;
    const uint32_t b_off = b_row * FROWB + ((lane >> 3) & 1) * 16;
    const int g2 = lane >> 3;
    const uint32_t v_off = (uint32_t)((g2 & 1) * 8 + (lane & 7)) * FROWB + (g2 >> 1) * 16;

    const int xr = x0 + wid * 16 + (lane >> 2);
    const int2* am0 = (const int2*)am + (size_t)(b * LL + xr) * (LL / 2);
    const int2* am1 = am0 + (size_t)8 * (LL / 2);
    const int2* pm2 = (const int2*)pmk + (size_t)b * (LL / 2);

    float m_s[2] = {-3.0e38f, -3.0e38f};
    float l_s[2] = {0.0f, 0.0f};
    float o[8][4];
#pragma unroll
    for (int nt = 0; nt < 8; ++nt)
#pragma unroll
        for (int r = 0; r < 4; ++r) o[nt][r] = 0.0f;

    const float SC = 0.125f;
    const float NEG = -1000000.0f;
    const int nkb = 4 * qb + 4;

    for (int kb = 0; kb < nkb; ++kb) {
        if (kb + 1 < nkb) {
            load_kv((kb + 1) & 1, (kb + 1) * 64);
            CP_WAIT(1);
        } else {
            CP_WAIT(0);
        }
        __syncthreads();

        const uint32_t kvb = sb + FSTG_OFF + (uint32_t)(kb & 1) * FSTG_SZ;

        // ---- S = Q @ K^T ----
        float s[8][4];
#pragma unroll
        for (int nt = 0; nt < 8; ++nt)
#pragma unroll
            for (int r = 0; r < 4; ++r) s[nt][r] = 0.0f;

#pragma unroll
        for (int kt = 0; kt < 4; ++kt) {
            uint32_t qh[4], ql[4];
            ldm_x4(qh, sb + FQ_HI + a_base + kt * 32);
            ldm_x4(ql, sb + FQ_LO + a_base + kt * 32);
            uint32_t khf[4][4], klf[4][4];
#pragma unroll
            for (int g = 0; g < 4; ++g) {
                uint32_t ko = kvb + (uint32_t)g * (16 * FROWB) + b_off + kt * 32;
                ldm_x4(khf[g], ko + FK_HI);
                ldm_x4(klf[g], ko + FK_LO);
            }
#pragma unroll
            for (int nt = 0; nt < 8; ++nt) {
                const uint32_t* bh = &khf[nt >> 1][(nt & 1) * 2];
                const uint32_t* bl = &klf[nt >> 1][(nt & 1) * 2];
                mma_bf16(s[nt], qh, bh);
                mma_bf16(s[nt], qh, bl);
                mma_bf16(s[nt], ql, bh);
            }
        }

        // ---- scale + masks (masks only needed near the diagonal) ----
        const int z0 = kb * 64;
        if (z0 + 63 > x0) {          // diagonal block: read real masks
            const int ci = (z0 >> 1) + (lane & 3);
#pragma unroll
            for (int nt = 0; nt < 8; ++nt) {
                int2 pm = pm2[ci + nt * 4];
                int2 u0 = am0[ci + nt * 4];
                int2 u1 = am1[ci + nt * 4];
                s[nt][0] = (u0.x != 0 && pm.x != 0) ? s[nt][0] * SC : NEG;
                s[nt][1] = (u0.y != 0 && pm.y != 0) ? s[nt][1] * SC : NEG;
                s[nt][2] = (u1.x != 0 && pm.x != 0) ? s[nt][2] * SC : NEG;
                s[nt][3] = (u1.y != 0 && pm.y != 0) ? s[nt][3] * SC : NEG;
            }
        } else {                     // interior: fully unmasked
#pragma unroll
            for (int nt = 0; nt < 8; ++nt) {
                s[nt][0] *= SC; s[nt][1] *= SC; s[nt][2] *= SC; s[nt][3] *= SC;
            }
        }

        // ---- online softmax ----
#pragma unroll
        for (int j = 0; j < 2; ++j) {
            const int j2 = j * 2;
            float rm = NEG;
#pragma unroll
            for (int nt = 0; nt < 8; ++nt)
                rm = fmaxf(rm, fmaxf(s[nt][j2], s[nt][j2 + 1]));
            rm = fmaxf(rm, __shfl_xor_sync(0xffffffffu, rm, 1));
            rm = fmaxf(rm, __shfl_xor_sync(0xffffffffu, rm, 2));
            float mn = fmaxf(m_s[j], rm);
            float corr = __expf(m_s[j] - mn);
            float ps = 0.0f;
#pragma unroll
            for (int nt = 0; nt < 8; ++nt) {
                float p0 = __expf(s[nt][j2] - mn);
                float p1 = __expf(s[nt][j2 + 1] - mn);
                s[nt][j2] = p0; s[nt][j2 + 1] = p1;
                ps += p0 + p1;
            }
            ps += __shfl_xor_sync(0xffffffffu, ps, 1);
            ps += __shfl_xor_sync(0xffffffffu, ps, 2);
            l_s[j] = l_s[j] * corr + ps;
            m_s[j] = mn;
#pragma unroll
            for (int nt = 0; nt < 8; ++nt) {
                o[nt][j2] *= corr;
                o[nt][j2 + 1] *= corr;
            }
        }

        // ---- O += P @ V ----
#pragma unroll
        for (int kt = 0; kt < 4; ++kt) {
            uint32_t ah[4], al[4];
            pack2(s[2 * kt][0], s[2 * kt][1], ah[0], al[0]);
            pack2(s[2 * kt][2], s[2 * kt][3], ah[1], al[1]);
            pack2(s[2 * kt + 1][0], s[2 * kt + 1][1], ah[2], al[2]);
            pack2(s[2 * kt + 1][2], s[2 * kt + 1][3], ah[3], al[3]);

            uint32_t vhf[4][4], vlf[4][4];
#pragma unroll
            for (int g = 0; g < 4; ++g) {
                uint32_t vo = kvb + (uint32_t)kt * (16 * FROWB) + (uint32_t)g * 32 + v_off;
                ldm_x4_t(vhf[g], vo + FV_HI);
                ldm_x4_t(vlf[g], vo + FV_LO);
            }
#pragma unroll
            for (int nt = 0; nt < 8; ++nt) {
                const uint32_t* bh = &vhf[nt >> 1][(nt & 1) * 2];
                const uint32_t* bl = &vlf[nt >> 1][(nt & 1) * 2];
                mma_bf16(o[nt], ah, bh);
                mma_bf16(o[nt], ah, bl);
                mma_bf16(o[nt], al, bh);
            }
        }
        __syncthreads();
    }

    // ---- epilogue ----
#pragma unroll
    for (int j = 0; j < 2; ++j) {
        float inv = 1.0f / l_s[j];
        size_t rowoff = (size_t)(b * LL + xr + j * 8) * DMODEL + h * DD + (lane & 3) * 2;
#pragma unroll
        for (int nt = 0; nt < 8; ++nt) {
            float c0 = o[nt][j * 2] * inv;
            float c1 = o[nt][j * 2 + 1] * inv;
            uint32_t uh, ul;
            pack2(c0, c1, uh, ul);
            *(uint32_t*)(Oh + rowoff + nt * 8) = uh;
            *(uint32_t*)(Ol + rowoff + nt * 8) = ul;
        }
    }
}

// ================================ launch ======================================
extern "C" void kernel_launch(void* const* d_in, const int* in_sizes, int n_in,
                              void* d_out, int out_size)
{
    const float* primary = (const float*)d_in[0];
    const float* context = (const float*)d_in[1];
    const int*   pmask   = (const int*)d_in[2];
    const int*   amask   = (const int*)d_in[3];
    const float* W_qs    = (const float*)d_in[4];
    const float* W_ks    = (const float*)d_in[5];
    const float* W_vs    = (const float*)d_in[6];
    const float* W_o     = (const float*)d_in[7];
    const float* b_o     = (const float*)d_in[8];
    float* out = (float*)d_out;

    __nv_bfloat16 *pH, *pL, *cH, *cL, *aH, *aL;
    __nv_bfloat16 *QH, *QL, *KH, *KL, *VH, *VL;
    __nv_bfloat16 *qH, *qL, *kH, *kL, *vH, *vL, *oH, *oL;
    cudaGetSymbolAddress((void**)&pH, g_prim_hi); cudaGetSymbolAddress((void**)&pL, g_prim_lo);
    cudaGetSymbolAddress((void**)&cH, g_ctx_hi);  cudaGetSymbolAddress((void**)&cL, g_ctx_lo);
    cudaGetSymbolAddress((void**)&aH, g_att_hi);  cudaGetSymbolAddress((void**)&aL, g_att_lo);
    cudaGetSymbolAddress((void**)&QH, g_Qhi);     cudaGetSymbolAddress((void**)&QL, g_Qlo);
    cudaGetSymbolAddress((void**)&KH, g_Khi);     cudaGetSymbolAddress((void**)&KL, g_Klo);
    cudaGetSymbolAddress((void**)&VH, g_Vhi);     cudaGetSymbolAddress((void**)&VL, g_Vlo);
    cudaGetSymbolAddress((void**)&qH, g_WqT_hi);  cudaGetSymbolAddress((void**)&qL, g_WqT_lo);
    cudaGetSymbolAddress((void**)&kH, g_WkT_hi);  cudaGetSymbolAddress((void**)&kL, g_WkT_lo);
    cudaGetSymbolAddress((void**)&vH, g_WvT_hi);  cudaGetSymbolAddress((void**)&vL, g_WvT_lo);
    cudaGetSymbolAddress((void**)&oH, g_WoT_hi);  cudaGetSymbolAddress((void**)&oL, g_WoT_lo);

    const int nact4 = (MROWS * DMODEL) / 4;
    split_kernel<<<nact4 / 256, 256>>>(primary, pH, pL, nact4);
    split_kernel<<<nact4 / 256, 256>>>(context, cH, cL, nact4);
    dim3 tb(32, 8), tg(DMODEL / 32, DMODEL / 32);
    split_T_kernel<<<tg, tb>>>(W_qs, qH, qL, DMODEL, DMODEL);
    split_T_kernel<<<tg, tb>>>(W_ks, kH, kL, DMODEL, DMODEL);
    split_T_kernel<<<tg, tb>>>(W_vs, vH, vL, DMODEL, DMODEL);
    split_T_kernel<<<tg, tb>>>(W_o,  oH, oL, DMODEL, DMODEL);

    size_t gsm = 2 * STAGE_P;   // 122880
    cudaFuncSetAttribute(gemm_bf16s<0>, cudaFuncAttributeMaxDynamicSharedMemorySize, (int)gsm);
    cudaFuncSetAttribute(gemm_bf16s<1>, cudaFuncAttributeMaxDynamicSharedMemorySize, (int)gsm);
    dim3 gg(DMODEL / 128, MROWS / 256);   // (8, 16)

    gemm_bf16s<1><<<gg, 512, gsm>>>(pH, pL, qH, qL, nullptr, QH, QL, nullptr, MROWS, DMODEL, DMODEL);
    gemm_bf16s<1><<<gg, 512, gsm>>>(cH, cL, kH, kL, nullptr, KH, KL, nullptr, MROWS, DMODEL, DMODEL);
    gemm_bf16s<1><<<gg, 512, gsm>>>(cH, cL, vH, vL, nullptr, VH, VL, nullptr, MROWS, DMODEL, DMODEL);

    cudaFuncSetAttribute(flash_mma, cudaFuncAttributeMaxDynamicSharedMemorySize, FSMEM_TOTAL);
    flash_mma<<<dim3(LL / 256, HH, BB), 512, FSMEM_TOTAL>>>(QH, QL, KH, KL, VH, VL,
                                                            amask, pmask, aH, aL);

    gemm_bf16s<0><<<gg, 512, gsm>>>(aH, aL, oH, oL, out, nullptr, nullptr, b_o, MROWS, DMODEL, DMODEL);
}

// round 6
// speedup vs baseline: 3.3582x; 1.3562x over previous
#include <cuda_runtime.h>
#include <cuda_fp16.h>
#include <math.h>
#include <stdint.h>

// Problem constants
#define BB 2
#define LL 2048
#define HH 16
#define DD 64
#define DMODEL 1024
#define MROWS (BB*LL)          // 4096

// ---------------- scratch (device globals: no allocations allowed) -------------
// activations: fp16 hi only (A-side of GEMMs)
__device__ __align__(256) __half g_prim_hi[(size_t)MROWS * DMODEL];
__device__ __align__(256) __half g_ctx_hi [(size_t)MROWS * DMODEL];
// projections
__device__ __align__(256) __half g_Qhi[(size_t)MROWS * DMODEL];
__device__ __align__(256) __half g_Khi[(size_t)MROWS * DMODEL];
__device__ __align__(256) __half g_Klo[(size_t)MROWS * DMODEL];
__device__ __align__(256) __half g_Vhi[(size_t)MROWS * DMODEL];
__device__ __align__(256) __half g_Vlo[(size_t)MROWS * DMODEL];
// attention output (A-side of final GEMM): hi only
__device__ __align__(256) __half g_att_hi[(size_t)MROWS * DMODEL];
// transposed weights [N,K] K-major, hi+lo
__device__ __align__(256) __half g_WqT_hi[(size_t)DMODEL * DMODEL];
__device__ __align__(256) __half g_WqT_lo[(size_t)DMODEL * DMODEL];
__device__ __align__(256) __half g_WkT_hi[(size_t)DMODEL * DMODEL];
__device__ __align__(256) __half g_WkT_lo[(size_t)DMODEL * DMODEL];
__device__ __align__(256) __half g_WvT_hi[(size_t)DMODEL * DMODEL];
__device__ __align__(256) __half g_WvT_lo[(size_t)DMODEL * DMODEL];
__device__ __align__(256) __half g_WoT_hi[(size_t)DMODEL * DMODEL];
__device__ __align__(256) __half g_WoT_lo[(size_t)DMODEL * DMODEL];

// ============================== PTX helpers ===================================
__device__ __forceinline__ uint32_t smem_u32(const void* p) {
    uint32_t a;
    asm("{ .reg .u64 t; cvta.to.shared.u64 t, %1; cvt.u32.u64 %0, t; }" : "=r"(a) : "l"(p));
    return a;
}
__device__ __forceinline__ void cp_async16(uint32_t sdst, const void* gsrc) {
    asm volatile("cp.async.cg.shared.global [%0], [%1], 16;" :: "r"(sdst), "l"(gsrc));
}
#define CP_COMMIT() asm volatile("cp.async.commit_group;" ::: "memory")
#define CP_WAIT(n)  asm volatile("cp.async.wait_group %0;" :: "n"(n) : "memory")

__device__ __forceinline__ void ldm_x4(uint32_t* r, uint32_t addr) {
    asm volatile("ldmatrix.sync.aligned.m8n8.x4.shared.b16 {%0,%1,%2,%3}, [%4];"
        : "=r"(r[0]), "=r"(r[1]), "=r"(r[2]), "=r"(r[3]) : "r"(addr));
}
__device__ __forceinline__ void ldm_x4_t(uint32_t* r, uint32_t addr) {
    asm volatile("ldmatrix.sync.aligned.m8n8.x4.trans.shared.b16 {%0,%1,%2,%3}, [%4];"
        : "=r"(r[0]), "=r"(r[1]), "=r"(r[2]), "=r"(r[3]) : "r"(addr));
}
__device__ __forceinline__ void mma_f16(float* c, const uint32_t* a, const uint32_t* b) {
    asm volatile("mma.sync.aligned.m16n8k16.row.col.f32.f16.f16.f32 "
        "{%0,%1,%2,%3}, {%4,%5,%6,%7}, {%8,%9}, {%0,%1,%2,%3};"
        : "+f"(c[0]), "+f"(c[1]), "+f"(c[2]), "+f"(c[3])
        : "r"(a[0]), "r"(a[1]), "r"(a[2]), "r"(a[3]), "r"(b[0]), "r"(b[1]));
}
// pack (p0,p1) -> f16x2 (low half = p0)
__device__ __forceinline__ uint32_t pack1h(float p0, float p1) {
    uint32_t h;
    asm("cvt.rn.f16x2.f32 %0, %1, %2;" : "=r"(h) : "f"(p1), "f"(p0));
    return h;
}
// pack hi + residual lo
__device__ __forceinline__ void pack2h(float p0, float p1, uint32_t& hi, uint32_t& lo) {
    hi = pack1h(p0, p1);
    __half2 t = *reinterpret_cast<__half2*>(&hi);
    float r0 = p0 - __half2float(t.x);
    float r1 = p1 - __half2float(t.y);
    lo = pack1h(r0, r1);
}

// ====================== fp32 -> fp16 split kernels ============================
// activations: hi only
__global__ __launch_bounds__(256)
void split_hi_kernel(const float* __restrict__ x, __half* __restrict__ hi, int n4)
{
    int i = blockIdx.x * blockDim.x + threadIdx.x;
    if (i >= n4) return;
    float4 v = *(const float4*)(x + (size_t)i * 4);
    __half h[4] = {__float2half_rn(v.x), __float2half_rn(v.y),
                   __float2half_rn(v.z), __float2half_rn(v.w)};
    *(uint2*)(hi + (size_t)i * 4) = *(uint2*)h;
}

// W[K,N] -> W^T[N,K] hi/lo
__global__ __launch_bounds__(256)
void split_T_kernel(const float* __restrict__ W, __half* __restrict__ hiT,
                    __half* __restrict__ loT, int K, int N)
{
    __shared__ float t[32][33];
    int k0 = blockIdx.y * 32, n0 = blockIdx.x * 32;
    int tx = threadIdx.x, ty = threadIdx.y;
#pragma unroll
    for (int j = 0; j < 4; ++j)
        t[ty + j * 8][tx] = W[(size_t)(k0 + ty + j * 8) * N + n0 + tx];
    __syncthreads();
#pragma unroll
    for (int j = 0; j < 4; ++j) {
        float v = t[tx][ty + j * 8];
        __half h = __float2half_rn(v);
        __half l = __float2half_rn(v - __half2float(h));
        size_t off = (size_t)(n0 + ty + j * 8) * K + k0 + tx;
        hiT[off] = h;
        loT[off] = l;
    }
}

// ====================== mma.sync fp16 2-product GEMM ==========================
// C = A_hi[M,K] @ (Bhi+Blo)^T, B stored [N,K] K-major.
// CTA 256x128, 512 threads (16 warps 4x4, warp tile 64x32), BK=32, double buffer.
#define GBK 32
#define TROW_B 80
#define OFF_A  0                   // 256*80 = 20480
#define OFF_BH 20480               // 128*80 = 10240
#define OFF_BL 30720
#define STAGE_P 40960

// OM: 0 = fp32 C + bias, 1 = f16 hi only, 2 = f16 hi+lo
template <int OM>
__global__ __launch_bounds__(512, 1)
void gemm_f16s(const __half* __restrict__ A, const __half* __restrict__ Bhi,
               const __half* __restrict__ Blo,
               float* __restrict__ C, __half* __restrict__ Chi,
               __half* __restrict__ Clo, const float* __restrict__ bias,
               int M, int N, int K)
{
    extern __shared__ char smem[];
    const uint32_t sb = smem_u32(smem);

    const int tid = threadIdx.x;
    const int wid = tid >> 5;
    const int lane = tid & 31;
    const int warp_m = wid >> 2;
    const int warp_n = wid & 3;
    const int bn = blockIdx.x * 128;
    const int bm = blockIdx.y * 256;

    const __half* aG = A + (size_t)bm * K;
    const __half* bHg = Bhi + (size_t)bn * K;
    const __half* bLg = Blo + (size_t)bn * K;

    float acc[4][4][4];
#pragma unroll
    for (int mt = 0; mt < 4; ++mt)
#pragma unroll
        for (int nt = 0; nt < 4; ++nt)
#pragma unroll
            for (int r = 0; r < 4; ++r) acc[mt][nt][r] = 0.0f;

    const int nch = K / GBK;

    const uint32_t a_row = (lane & 7) + ((lane >> 3) & 1) * 8;
    const uint32_t a_off = a_row * TROW_B + (lane >> 4) * 16;
    const uint32_t b_row = (lane & 7) + (lane >> 4) * 8;
    const uint32_t b_off = b_row * TROW_B + ((lane >> 3) & 1) * 16;

    auto load_chunk = [&](int stage, int k0) {
        uint32_t base = sb + (uint32_t)stage * STAGE_P;
        // A: 1024 16B lines, 2 per thread
#pragma unroll
        for (int t = 0; t < 2; ++t) {
            int l = tid * 2 + t;
            int row = l >> 2, cb = l & 3;
            cp_async16(base + OFF_A + (uint32_t)row * TROW_B + cb * 16,
                       aG + (size_t)row * K + k0 + cb * 8);
        }
        // B hi/lo: 512 lines each, 1 per thread
        {
            int row = tid >> 2, cb = tid & 3;
            uint32_t doff = (uint32_t)row * TROW_B + cb * 16;
            size_t goff = (size_t)row * K + k0 + cb * 8;
            cp_async16(base + OFF_BH + doff, bHg + goff);
            cp_async16(base + OFF_BL + doff, bLg + goff);
        }
        CP_COMMIT();
    };

    load_chunk(0, 0);

    for (int i = 0; i < nch; ++i) {
        if (i + 1 < nch) {
            load_chunk((i + 1) & 1, (i + 1) * GBK);
            CP_WAIT(1);
        } else {
            CP_WAIT(0);
        }
        __syncthreads();

        uint32_t base = sb + (uint32_t)(i & 1) * STAGE_P;
        uint32_t aB  = base + OFF_A  + warp_m * 64 * TROW_B + a_off;
        uint32_t bHb = base + OFF_BH + warp_n * 32 * TROW_B + b_off;
        uint32_t bLb = base + OFF_BL + warp_n * 32 * TROW_B + b_off;

#pragma unroll
        for (int ks = 0; ks < 2; ++ks) {
            uint32_t aF[4][4], bH[2][4], bL[2][4];
#pragma unroll
            for (int mt = 0; mt < 4; ++mt)
                ldm_x4(aF[mt], aB + mt * 16 * TROW_B + ks * 32);
#pragma unroll
            for (int n16 = 0; n16 < 2; ++n16) {
                ldm_x4(bH[n16], bHb + n16 * 16 * TROW_B + ks * 32);
                ldm_x4(bL[n16], bLb + n16 * 16 * TROW_B + ks * 32);
            }
#pragma unroll
            for (int mt = 0; mt < 4; ++mt)
#pragma unroll
                for (int nt = 0; nt < 4; ++nt) {
                    const uint32_t* bh = &bH[nt >> 1][(nt & 1) * 2];
                    const uint32_t* bl = &bL[nt >> 1][(nt & 1) * 2];
                    mma_f16(acc[mt][nt], aF[mt], bh);
                    mma_f16(acc[mt][nt], aF[mt], bl);
                }
        }
        __syncthreads();
    }

    const int r0 = bm + warp_m * 64 + (lane >> 2);
    const int c0 = bn + warp_n * 32 + (lane & 3) * 2;
#pragma unroll
    for (int mt = 0; mt < 4; ++mt) {
#pragma unroll
        for (int nt = 0; nt < 4; ++nt) {
            int col = c0 + nt * 8;
            if (OM == 0) {
                float bx = bias[col], by = bias[col + 1];
                float2 v0 = make_float2(acc[mt][nt][0] + bx, acc[mt][nt][1] + by);
                float2 v1 = make_float2(acc[mt][nt][2] + bx, acc[mt][nt][3] + by);
                *(float2*)(C + (size_t)(r0 + mt * 16) * N + col) = v0;
                *(float2*)(C + (size_t)(r0 + mt * 16 + 8) * N + col) = v1;
            } else if (OM == 1) {
                *(uint32_t*)(Chi + (size_t)(r0 + mt * 16) * N + col) =
                    pack1h(acc[mt][nt][0], acc[mt][nt][1]);
                *(uint32_t*)(Chi + (size_t)(r0 + mt * 16 + 8) * N + col) =
                    pack1h(acc[mt][nt][2], acc[mt][nt][3]);
            } else {
                uint32_t uh, ul;
                pack2h(acc[mt][nt][0], acc[mt][nt][1], uh, ul);
                *(uint32_t*)(Chi + (size_t)(r0 + mt * 16) * N + col) = uh;
                *(uint32_t*)(Clo + (size_t)(r0 + mt * 16) * N + col) = ul;
                pack2h(acc[mt][nt][2], acc[mt][nt][3], uh, ul);
                *(uint32_t*)(Chi + (size_t)(r0 + mt * 16 + 8) * N + col) = uh;
                *(uint32_t*)(Clo + (size_t)(r0 + mt * 16 + 8) * N + col) = ul;
            }
        }
    }
}

// ===================== Flash attention on mma.sync (fp16) =====================
// CTA: 256 queries x one (b,h), 512 threads (16 warps x 16 rows).
// S = Qhi @ (Khi+Klo)^T  (2 MMAs), fp32 softmax, O += Phi @ (Vhi+Vlo) (2 MMAs).
#define FROWB 144
#define FQ_HI 0                    // 256*144 = 36864
#define FSTG_OFF 36864
#define FSTG_SZ 36864              // 4 arrays * 64*144
#define FK_HI 0
#define FK_LO 9216
#define FV_HI 18432
#define FV_LO 27648
#define FSMEM_TOTAL (FSTG_OFF + 2 * FSTG_SZ)   // 110592

__global__ __launch_bounds__(512, 1)
void flash_mma(const __half* __restrict__ Qh,
               const __half* __restrict__ Kh, const __half* __restrict__ Kl,
               const __half* __restrict__ Vh, const __half* __restrict__ Vl,
               const int* __restrict__ am, const int* __restrict__ pmk,
               __half* __restrict__ Oh)
{
    extern __shared__ char smem[];
    const uint32_t sb = smem_u32(smem);
    const int tid = threadIdx.x, wid = tid >> 5, lane = tid & 31;
    const int qb = (int)gridDim.x - 1 - (int)blockIdx.x;
    const int h = blockIdx.y, b = blockIdx.z;
    const int x0 = qb * 256;

    // Q tile hi: 2048 lines, 4 per thread
#pragma unroll
    for (int t = 0; t < 4; ++t) {
        int l = tid + t * 512;
        int r = l >> 3, c = l & 7;
        cp_async16(sb + FQ_HI + (uint32_t)r * FROWB + c * 16,
                   Qh + (size_t)(b * LL + x0 + r) * DMODEL + h * DD + c * 8);
    }
    auto load_kv = [&](int stg, int z0) {
        uint32_t base = sb + FSTG_OFF + (uint32_t)stg * FSTG_SZ;
#pragma unroll
        for (int t = 0; t < 4; ++t) {
            int l = tid + t * 512;
            int arr = l >> 9, r = (l >> 3) & 63, c = l & 7;
            const __half* src = (arr & 2) ? ((arr & 1) ? Vl : Vh)
                                          : ((arr & 1) ? Kl : Kh);
            cp_async16(base + (uint32_t)arr * 9216 + (uint32_t)r * FROWB + c * 16,
                       src + (size_t)(b * LL + z0 + r) * DMODEL + h * DD + c * 8);
        }
        CP_COMMIT();
    };
    load_kv(0, 0);

    const uint32_t a_row = (lane & 7) + ((lane >> 3) & 1) * 8;
    const uint32_t a_base = (uint32_t)(wid * 16 + a_row) * FROWB + (lane >> 4) * 16;
    const uint32_t b_row = (lane & 7) + (lane >> 4) * 8;
    const uint32_t b_off = b_row * FROWB + ((lane >> 3) & 1) * 16;
    const int g2 = lane >> 3;
    const uint32_t v_off = (uint32_t)((g2 & 1) * 8 + (lane & 7)) * FROWB + (g2 >> 1) * 16;

    const int xr = x0 + wid * 16 + (lane >> 2);
    const int2* am0 = (const int2*)am + (size_t)(b * LL + xr) * (LL / 2);
    const int2* am1 = am0 + (size_t)8 * (LL / 2);
    const int2* pm2 = (const int2*)pmk + (size_t)b * (LL / 2);

    float m_s[2] = {-3.0e38f, -3.0e38f};
    float l_s[2] = {0.0f, 0.0f};
    float o[8][4];
#pragma unroll
    for (int nt = 0; nt < 8; ++nt)
#pragma unroll
        for (int r = 0; r < 4; ++r) o[nt][r] = 0.0f;

    const float SC = 0.125f;
    const float NEG = -1000000.0f;
    const int nkb = 4 * qb + 4;

    for (int kb = 0; kb < nkb; ++kb) {
        if (kb + 1 < nkb) {
            load_kv((kb + 1) & 1, (kb + 1) * 64);
            CP_WAIT(1);
        } else {
            CP_WAIT(0);
        }
        __syncthreads();

        const uint32_t kvb = sb + FSTG_OFF + (uint32_t)(kb & 1) * FSTG_SZ;

        // ---- S = Q @ K^T ----
        float s[8][4];
#pragma unroll
        for (int nt = 0; nt < 8; ++nt)
#pragma unroll
            for (int r = 0; r < 4; ++r) s[nt][r] = 0.0f;

#pragma unroll
        for (int kt = 0; kt < 4; ++kt) {
            uint32_t qf[4];
            ldm_x4(qf, sb + FQ_HI + a_base + kt * 32);
            uint32_t khf[4][4], klf[4][4];
#pragma unroll
            for (int g = 0; g < 4; ++g) {
                uint32_t ko = kvb + (uint32_t)g * (16 * FROWB) + b_off + kt * 32;
                ldm_x4(khf[g], ko + FK_HI);
                ldm_x4(klf[g], ko + FK_LO);
            }
#pragma unroll
            for (int nt = 0; nt < 8; ++nt) {
                mma_f16(s[nt], qf, &khf[nt >> 1][(nt & 1) * 2]);
                mma_f16(s[nt], qf, &klf[nt >> 1][(nt & 1) * 2]);
            }
        }

        // ---- scale + masks (real masks only near the diagonal) ----
        const int z0 = kb * 64;
        if (z0 + 63 > x0) {
            const int ci = (z0 >> 1) + (lane & 3);
#pragma unroll
            for (int nt = 0; nt < 8; ++nt) {
                int2 pm = pm2[ci + nt * 4];
                int2 u0 = am0[ci + nt * 4];
                int2 u1 = am1[ci + nt * 4];
                s[nt][0] = (u0.x != 0 && pm.x != 0) ? s[nt][0] * SC : NEG;
                s[nt][1] = (u0.y != 0 && pm.y != 0) ? s[nt][1] * SC : NEG;
                s[nt][2] = (u1.x != 0 && pm.x != 0) ? s[nt][2] * SC : NEG;
                s[nt][3] = (u1.y != 0 && pm.y != 0) ? s[nt][3] * SC : NEG;
            }
        } else {
#pragma unroll
            for (int nt = 0; nt < 8; ++nt) {
                s[nt][0] *= SC; s[nt][1] *= SC; s[nt][2] *= SC; s[nt][3] *= SC;
            }
        }

        // ---- online softmax ----
#pragma unroll
        for (int j = 0; j < 2; ++j) {
            const int j2 = j * 2;
            float rm = NEG;
#pragma unroll
            for (int nt = 0; nt < 8; ++nt)
                rm = fmaxf(rm, fmaxf(s[nt][j2], s[nt][j2 + 1]));
            rm = fmaxf(rm, __shfl_xor_sync(0xffffffffu, rm, 1));
            rm = fmaxf(rm, __shfl_xor_sync(0xffffffffu, rm, 2));
            float mn = fmaxf(m_s[j], rm);
            float corr = __expf(m_s[j] - mn);
            float ps = 0.0f;
#pragma unroll
            for (int nt = 0; nt < 8; ++nt) {
                float p0 = __expf(s[nt][j2] - mn);
                float p1 = __expf(s[nt][j2 + 1] - mn);
                s[nt][j2] = p0; s[nt][j2 + 1] = p1;
                ps += p0 + p1;
            }
            ps += __shfl_xor_sync(0xffffffffu, ps, 1);
            ps += __shfl_xor_sync(0xffffffffu, ps, 2);
            l_s[j] = l_s[j] * corr + ps;
            m_s[j] = mn;
#pragma unroll
            for (int nt = 0; nt < 8; ++nt) {
                o[nt][j2] *= corr;
                o[nt][j2 + 1] *= corr;
            }
        }

        // ---- O += P @ V ----
#pragma unroll
        for (int kt = 0; kt < 4; ++kt) {
            uint32_t ah[4];
            ah[0] = pack1h(s[2 * kt][0], s[2 * kt][1]);
            ah[1] = pack1h(s[2 * kt][2], s[2 * kt][3]);
            ah[2] = pack1h(s[2 * kt + 1][0], s[2 * kt + 1][1]);
            ah[3] = pack1h(s[2 * kt + 1][2], s[2 * kt + 1][3]);

            uint32_t vhf[4][4], vlf[4][4];
#pragma unroll
            for (int g = 0; g < 4; ++g) {
                uint32_t vo = kvb + (uint32_t)kt * (16 * FROWB) + (uint32_t)g * 32 + v_off;
                ldm_x4_t(vhf[g], vo + FV_HI);
                ldm_x4_t(vlf[g], vo + FV_LO);
            }
#pragma unroll
            for (int nt = 0; nt < 8; ++nt) {
                mma_f16(o[nt], ah, &vhf[nt >> 1][(nt & 1) * 2]);
                mma_f16(o[nt], ah, &vlf[nt >> 1][(nt & 1) * 2]);
            }
        }
        __syncthreads();
    }

    // ---- epilogue: normalize, store fp16 hi ----
#pragma unroll
    for (int j = 0; j < 2; ++j) {
        float inv = 1.0f / l_s[j];
        size_t rowoff = (size_t)(b * LL + xr + j * 8) * DMODEL + h * DD + (lane & 3) * 2;
#pragma unroll
        for (int nt = 0; nt < 8; ++nt) {
            *(uint32_t*)(Oh + rowoff + nt * 8) =
                pack1h(o[nt][j * 2] * inv, o[nt][j * 2 + 1] * inv);
        }
    }
}

// ================================ launch ======================================
extern "C" void kernel_launch(void* const* d_in, const int* in_sizes, int n_in,
                              void* d_out, int out_size)
{
    const float* primary = (const float*)d_in[0];
    const float* context = (const float*)d_in[1];
    const int*   pmask   = (const int*)d_in[2];
    const int*   amask   = (const int*)d_in[3];
    const float* W_qs    = (const float*)d_in[4];
    const float* W_ks    = (const float*)d_in[5];
    const float* W_vs    = (const float*)d_in[6];
    const float* W_o     = (const float*)d_in[7];
    const float* b_o     = (const float*)d_in[8];
    float* out = (float*)d_out;

    __half *pH, *cH, *aH;
    __half *QH, *KH, *KL, *VH, *VL;
    __half *qH, *qL, *kH, *kL, *vH, *vL, *oH, *oL;
    cudaGetSymbolAddress((void**)&pH, g_prim_hi);
    cudaGetSymbolAddress((void**)&cH, g_ctx_hi);
    cudaGetSymbolAddress((void**)&aH, g_att_hi);
    cudaGetSymbolAddress((void**)&QH, g_Qhi);
    cudaGetSymbolAddress((void**)&KH, g_Khi);     cudaGetSymbolAddress((void**)&KL, g_Klo);
    cudaGetSymbolAddress((void**)&VH, g_Vhi);     cudaGetSymbolAddress((void**)&VL, g_Vlo);
    cudaGetSymbolAddress((void**)&qH, g_WqT_hi);  cudaGetSymbolAddress((void**)&qL, g_WqT_lo);
    cudaGetSymbolAddress((void**)&kH, g_WkT_hi);  cudaGetSymbolAddress((void**)&kL, g_WkT_lo);
    cudaGetSymbolAddress((void**)&vH, g_WvT_hi);  cudaGetSymbolAddress((void**)&vL, g_WvT_lo);
    cudaGetSymbolAddress((void**)&oH, g_WoT_hi);  cudaGetSymbolAddress((void**)&oL, g_WoT_lo);

    const int nact4 = (MROWS * DMODEL) / 4;
    split_hi_kernel<<<nact4 / 256, 256>>>(primary, pH, nact4);
    split_hi_kernel<<<nact4 / 256, 256>>>(context, cH, nact4);
    dim3 tb(32, 8), tg(DMODEL / 32, DMODEL / 32);
    split_T_kernel<<<tg, tb>>>(W_qs, qH, qL, DMODEL, DMODEL);
    split_T_kernel<<<tg, tb>>>(W_ks, kH, kL, DMODEL, DMODEL);
    split_T_kernel<<<tg, tb>>>(W_vs, vH, vL, DMODEL, DMODEL);
    split_T_kernel<<<tg, tb>>>(W_o,  oH, oL, DMODEL, DMODEL);

    size_t gsm = 2 * STAGE_P;   // 81920
    cudaFuncSetAttribute(gemm_f16s<0>, cudaFuncAttributeMaxDynamicSharedMemorySize, (int)gsm);
    cudaFuncSetAttribute(gemm_f16s<1>, cudaFuncAttributeMaxDynamicSharedMemorySize, (int)gsm);
    cudaFuncSetAttribute(gemm_f16s<2>, cudaFuncAttributeMaxDynamicSharedMemorySize, (int)gsm);
    dim3 gg(DMODEL / 128, MROWS / 256);   // (8, 16)

    gemm_f16s<1><<<gg, 512, gsm>>>(pH, qH, qL, nullptr, QH, nullptr, nullptr, MROWS, DMODEL, DMODEL);
    gemm_f16s<2><<<gg, 512, gsm>>>(cH, kH, kL, nullptr, KH, KL, nullptr, MROWS, DMODEL, DMODEL);
    gemm_f16s<2><<<gg, 512, gsm>>>(cH, vH, vL, nullptr, VH, VL, nullptr, MROWS, DMODEL, DMODEL);

    cudaFuncSetAttribute(flash_mma, cudaFuncAttributeMaxDynamicSharedMemorySize, FSMEM_TOTAL);
    flash_mma<<<dim3(LL / 256, HH, BB), 512, FSMEM_TOTAL>>>(QH, KH, KL, VH, VL,
                                                            amask, pmask, aH);

    gemm_f16s<0><<<gg, 512, gsm>>>(aH, oH, oL, out, nullptr, nullptr, b_o, MROWS, DMODEL, DMODEL);
}

// round 8
// speedup vs baseline: 5.0329x; 1.4987x over previous
#include <cuda_runtime.h>
#include <cuda_fp16.h>
#include <math.h>
#include <stdint.h>

// Problem constants
#define BB 2
#define LL 2048
#define HH 16
#define DD 64
#define DMODEL 1024
#define MROWS (BB*LL)          // 4096

// ---------------- scratch (device globals: no allocations allowed) -------------
__device__ __align__(256) __half g_prim_hi[(size_t)MROWS * DMODEL];
__device__ __align__(256) __half g_ctx_hi [(size_t)MROWS * DMODEL];
__device__ __align__(256) __half g_Qhi[(size_t)MROWS * DMODEL];
__device__ __align__(256) __half g_Khi[(size_t)MROWS * DMODEL];
__device__ __align__(256) __half g_Vhi[(size_t)MROWS * DMODEL];
__device__ __align__(256) __half g_att_hi[(size_t)MROWS * DMODEL];
// transposed weights [N,K] K-major (fp16)
__device__ __align__(256) __half g_WqT_hi[(size_t)DMODEL * DMODEL];
__device__ __align__(256) __half g_WkT_hi[(size_t)DMODEL * DMODEL];
__device__ __align__(256) __half g_WvT_hi[(size_t)DMODEL * DMODEL];
__device__ __align__(256) __half g_WoT_hi[(size_t)DMODEL * DMODEL];

// ============================== PTX helpers ===================================
__device__ __forceinline__ uint32_t smem_u32(const void* p) {
    uint32_t a;
    asm("{ .reg .u64 t; cvta.to.shared.u64 t, %1; cvt.u32.u64 %0, t; }" : "=r"(a) : "l"(p));
    return a;
}
__device__ __forceinline__ void cp_async16(uint32_t sdst, const void* gsrc) {
    asm volatile("cp.async.cg.shared.global [%0], [%1], 16;" :: "r"(sdst), "l"(gsrc));
}
#define CP_COMMIT() asm volatile("cp.async.commit_group;" ::: "memory")
#define CP_WAIT(n)  asm volatile("cp.async.wait_group %0;" :: "n"(n) : "memory")

__device__ __forceinline__ void ldm_x4(uint32_t* r, uint32_t addr) {
    asm volatile("ldmatrix.sync.aligned.m8n8.x4.shared.b16 {%0,%1,%2,%3}, [%4];"
        : "=r"(r[0]), "=r"(r[1]), "=r"(r[2]), "=r"(r[3]) : "r"(addr));
}
__device__ __forceinline__ void ldm_x4_t(uint32_t* r, uint32_t addr) {
    asm volatile("ldmatrix.sync.aligned.m8n8.x4.trans.shared.b16 {%0,%1,%2,%3}, [%4];"
        : "=r"(r[0]), "=r"(r[1]), "=r"(r[2]), "=r"(r[3]) : "r"(addr));
}
__device__ __forceinline__ void mma_f16(float* c, const uint32_t* a, const uint32_t* b) {
    asm volatile("mma.sync.aligned.m16n8k16.row.col.f32.f16.f16.f32 "
        "{%0,%1,%2,%3}, {%4,%5,%6,%7}, {%8,%9}, {%0,%1,%2,%3};"
        : "+f"(c[0]), "+f"(c[1]), "+f"(c[2]), "+f"(c[3])
        : "r"(a[0]), "r"(a[1]), "r"(a[2]), "r"(a[3]), "r"(b[0]), "r"(b[1]));
}
__device__ __forceinline__ uint32_t pack1h(float p0, float p1) {
    uint32_t h;
    asm("cvt.rn.f16x2.f32 %0, %1, %2;" : "=r"(h) : "f"(p1), "f"(p0));
    return h;
}

// ====================== fp32 -> fp16 conversion kernels =======================
__global__ __launch_bounds__(256)
void split_hi_kernel(const float* __restrict__ x, __half* __restrict__ hi, int n4)
{
    int i = blockIdx.x * blockDim.x + threadIdx.x;
    if (i >= n4) return;
    float4 v = *(const float4*)(x + (size_t)i * 4);
    __half h[4] = {__float2half_rn(v.x), __float2half_rn(v.y),
                   __float2half_rn(v.z), __float2half_rn(v.w)};
    *(uint2*)(hi + (size_t)i * 4) = *(uint2*)h;
}

// W[K,N] -> W^T[N,K] fp16
__global__ __launch_bounds__(256)
void split_T_kernel(const float* __restrict__ W, __half* __restrict__ hiT, int K, int N)
{
    __shared__ float t[32][33];
    int k0 = blockIdx.y * 32, n0 = blockIdx.x * 32;
    int tx = threadIdx.x, ty = threadIdx.y;
#pragma unroll
    for (int j = 0; j < 4; ++j)
        t[ty + j * 8][tx] = W[(size_t)(k0 + ty + j * 8) * N + n0 + tx];
    __syncthreads();
#pragma unroll
    for (int j = 0; j < 4; ++j) {
        size_t off = (size_t)(n0 + ty + j * 8) * K + k0 + tx;
        hiT[off] = __float2half_rn(t[tx][ty + j * 8]);
    }
}

// ====================== mma.sync fp16 GEMM ====================================
// C = A[M,K] @ B^T, B stored [N,K] K-major.
// CTA 256x128, 512 threads (16 warps 4x4, warp tile 64x32), BK=32, double buffer.
#define GBK 32
#define TROW_B 80
#define OFF_A  0                   // 256*80 = 20480
#define OFF_B  20480               // 128*80 = 10240
#define STAGE_P 30720

// OM: 0 = fp32 C + bias, 1 = f16 out
template <int OM>
__global__ __launch_bounds__(512, 1)
void gemm_f16(const __half* __restrict__ A, const __half* __restrict__ B,
              float* __restrict__ C, __half* __restrict__ Ch,
              const float* __restrict__ bias, int M, int N, int K)
{
    extern __shared__ char smem[];
    const uint32_t sb = smem_u32(smem);

    const int tid = threadIdx.x;
    const int wid = tid >> 5;
    const int lane = tid & 31;
    const int warp_m = wid >> 2;
    const int warp_n = wid & 3;
    const int bn = blockIdx.x * 128;
    const int bm = blockIdx.y * 256;

    const __half* aG = A + (size_t)bm * K;
    const __half* bG = B + (size_t)bn * K;

    float acc[4][4][4];
#pragma unroll
    for (int mt = 0; mt < 4; ++mt)
#pragma unroll
        for (int nt = 0; nt < 4; ++nt)
#pragma unroll
            for (int r = 0; r < 4; ++r) acc[mt][nt][r] = 0.0f;

    const int nch = K / GBK;

    const uint32_t a_row = (lane & 7) + ((lane >> 3) & 1) * 8;
    const uint32_t a_off = a_row * TROW_B + (lane >> 4) * 16;
    const uint32_t b_row = (lane & 7) + (lane >> 4) * 8;
    const uint32_t b_off = b_row * TROW_B + ((lane >> 3) & 1) * 16;

    auto load_chunk = [&](int stage, int k0) {
        uint32_t base = sb + (uint32_t)stage * STAGE_P;
        // A: 1024 16B lines, 2 per thread
#pragma unroll
        for (int t = 0; t < 2; ++t) {
            int l = tid * 2 + t;
            int row = l >> 2, cb = l & 3;
            cp_async16(base + OFF_A + (uint32_t)row * TROW_B + cb * 16,
                       aG + (size_t)row * K + k0 + cb * 8);
        }
        // B: 512 lines, 1 per thread
        {
            int row = tid >> 2, cb = tid & 3;
            cp_async16(base + OFF_B + (uint32_t)row * TROW_B + cb * 16,
                       bG + (size_t)row * K + k0 + cb * 8);
        }
        CP_COMMIT();
    };

    load_chunk(0, 0);

    for (int i = 0; i < nch; ++i) {
        if (i + 1 < nch) {
            load_chunk((i + 1) & 1, (i + 1) * GBK);
            CP_WAIT(1);
        } else {
            CP_WAIT(0);
        }
        __syncthreads();

        uint32_t base = sb + (uint32_t)(i & 1) * STAGE_P;
        uint32_t aB = base + OFF_A + warp_m * 64 * TROW_B + a_off;
        uint32_t bB = base + OFF_B + warp_n * 32 * TROW_B + b_off;

#pragma unroll
        for (int ks = 0; ks < 2; ++ks) {
            uint32_t aF[4][4], bF[2][4];
#pragma unroll
            for (int mt = 0; mt < 4; ++mt)
                ldm_x4(aF[mt], aB + mt * 16 * TROW_B + ks * 32);
#pragma unroll
            for (int n16 = 0; n16 < 2; ++n16)
                ldm_x4(bF[n16], bB + n16 * 16 * TROW_B + ks * 32);
#pragma unroll
            for (int mt = 0; mt < 4; ++mt)
#pragma unroll
                for (int nt = 0; nt < 4; ++nt)
                    mma_f16(acc[mt][nt], aF[mt], &bF[nt >> 1][(nt & 1) * 2]);
        }
        __syncthreads();
    }

    const int r0 = bm + warp_m * 64 + (lane >> 2);
    const int c0 = bn + warp_n * 32 + (lane & 3) * 2;
#pragma unroll
    for (int mt = 0; mt < 4; ++mt) {
#pragma unroll
        for (int nt = 0; nt < 4; ++nt) {
            int col = c0 + nt * 8;
            if (OM == 0) {
                float bx = bias[col], by = bias[col + 1];
                float2 v0 = make_float2(acc[mt][nt][0] + bx, acc[mt][nt][1] + by);
                float2 v1 = make_float2(acc[mt][nt][2] + bx, acc[mt][nt][3] + by);
                *(float2*)(C + (size_t)(r0 + mt * 16) * N + col) = v0;
                *(float2*)(C + (size_t)(r0 + mt * 16 + 8) * N + col) = v1;
            } else {
                *(uint32_t*)(Ch + (size_t)(r0 + mt * 16) * N + col) =
                    pack1h(acc[mt][nt][0], acc[mt][nt][1]);
                *(uint32_t*)(Ch + (size_t)(r0 + mt * 16 + 8) * N + col) =
                    pack1h(acc[mt][nt][2], acc[mt][nt][3]);
            }
        }
    }
}

// ===================== Flash attention on mma.sync (fp16) =====================
// CTA: 256 queries x one (b,h), 512 threads (16 warps x 16 rows).
// S = Q @ K^T (1 MMA set), fp32 softmax, O += P @ V (1 MMA set).
#define FROWB 144
#define FQ_HI 0                    // 256*144 = 36864
#define FSTG_OFF 36864
#define FSTG_SZ 18432              // 2 arrays * 64*144
#define FK_OFF 0
#define FV_OFF 9216
#define FSMEM_TOTAL (FSTG_OFF + 2 * FSTG_SZ)   // 73728

__global__ __launch_bounds__(512, 1)
void flash_mma(const __half* __restrict__ Qh,
               const __half* __restrict__ Kh, const __half* __restrict__ Vh,
               const int* __restrict__ am, const int* __restrict__ pmk,
               __half* __restrict__ Oh)
{
    extern __shared__ char smem[];
    const uint32_t sb = smem_u32(smem);
    const int tid = threadIdx.x, wid = tid >> 5, lane = tid & 31;
    const int qb = (int)gridDim.x - 1 - (int)blockIdx.x;
    const int h = blockIdx.y, b = blockIdx.z;
    const int x0 = qb * 256;

    // Q tile: 2048 lines, 4 per thread
#pragma unroll
    for (int t = 0; t < 4; ++t) {
        int l = tid + t * 512;
        int r = l >> 3, c = l & 7;
        cp_async16(sb + FQ_HI + (uint32_t)r * FROWB + c * 16,
                   Qh + (size_t)(b * LL + x0 + r) * DMODEL + h * DD + c * 8);
    }
    auto load_kv = [&](int stg, int z0) {
        uint32_t base = sb + FSTG_OFF + (uint32_t)stg * FSTG_SZ;
        // K + V: 1024 lines, 2 per thread
#pragma unroll
        for (int t = 0; t < 2; ++t) {
            int l = tid + t * 512;
            int arr = l >> 9, r = (l >> 3) & 63, c = l & 7;
            const __half* src = arr ? Vh : Kh;
            cp_async16(base + (uint32_t)arr * 9216 + (uint32_t)r * FROWB + c * 16,
                       src + (size_t)(b * LL + z0 + r) * DMODEL + h * DD + c * 8);
        }
        CP_COMMIT();
    };
    load_kv(0, 0);

    const uint32_t a_row = (lane & 7) + ((lane >> 3) & 1) * 8;
    const uint32_t a_base = (uint32_t)(wid * 16 + a_row) * FROWB + (lane >> 4) * 16;
    const uint32_t b_row = (lane & 7) + (lane >> 4) * 8;
    const uint32_t b_off = b_row * FROWB + ((lane >> 3) & 1) * 16;
    const int g2 = lane >> 3;
    const uint32_t v_off = (uint32_t)((g2 & 1) * 8 + (lane & 7)) * FROWB + (g2 >> 1) * 16;

    const int xr = x0 + wid * 16 + (lane >> 2);
    const int2* am0 = (const int2*)am + (size_t)(b * LL + xr) * (LL / 2);
    const int2* am1 = am0 + (size_t)8 * (LL / 2);
    const int2* pm2 = (const int2*)pmk + (size_t)b * (LL / 2);

    float m_s[2] = {-3.0e38f, -3.0e38f};
    float l_s[2] = {0.0f, 0.0f};
    float o[8][4];
#pragma unroll
    for (int nt = 0; nt < 8; ++nt)
#pragma unroll
        for (int r = 0; r < 4; ++r) o[nt][r] = 0.0f;

    const float SC = 0.125f;
    const float NEG = -1000000.0f;
    const int nkb = 4 * qb + 4;

    for (int kb = 0; kb < nkb; ++kb) {
        if (kb + 1 < nkb) {
            load_kv((kb + 1) & 1, (kb + 1) * 64);
            CP_WAIT(1);
        } else {
            CP_WAIT(0);
        }
        __syncthreads();

        const uint32_t kvb = sb + FSTG_OFF + (uint32_t)(kb & 1) * FSTG_SZ;

        // ---- S = Q @ K^T ----
        float s[8][4];
#pragma unroll
        for (int nt = 0; nt < 8; ++nt)
#pragma unroll
            for (int r = 0; r < 4; ++r) s[nt][r] = 0.0f;

#pragma unroll
        for (int kt = 0; kt < 4; ++kt) {
            uint32_t qf[4];
            ldm_x4(qf, sb + FQ_HI + a_base + kt * 32);
            uint32_t kf[4][4];
#pragma unroll
            for (int g = 0; g < 4; ++g)
                ldm_x4(kf[g], kvb + FK_OFF + (uint32_t)g * (16 * FROWB) + b_off + kt * 32);
#pragma unroll
            for (int nt = 0; nt < 8; ++nt)
                mma_f16(s[nt], qf, &kf[nt >> 1][(nt & 1) * 2]);
        }

        // ---- scale + masks (real masks only near the diagonal) ----
        const int z0 = kb * 64;
        if (z0 + 63 > x0) {
            const int ci = (z0 >> 1) + (lane & 3);
#pragma unroll
            for (int nt = 0; nt < 8; ++nt) {
                int2 pm = pm2[ci + nt * 4];
                int2 u0 = am0[ci + nt * 4];
                int2 u1 = am1[ci + nt * 4];
                s[nt][0] = (u0.x != 0 && pm.x != 0) ? s[nt][0] * SC : NEG;
                s[nt][1] = (u0.y != 0 && pm.y != 0) ? s[nt][1] * SC : NEG;
                s[nt][2] = (u1.x != 0 && pm.x != 0) ? s[nt][2] * SC : NEG;
                s[nt][3] = (u1.y != 0 && pm.y != 0) ? s[nt][3] * SC : NEG;
            }
        } else {
#pragma unroll
            for (int nt = 0; nt < 8; ++nt) {
                s[nt][0] *= SC; s[nt][1] *= SC; s[nt][2] *= SC; s[nt][3] *= SC;
            }
        }

        // ---- online softmax ----
#pragma unroll
        for (int j = 0; j < 2; ++j) {
            const int j2 = j * 2;
            float rm = NEG;
#pragma unroll
            for (int nt = 0; nt < 8; ++nt)
                rm = fmaxf(rm, fmaxf(s[nt][j2], s[nt][j2 + 1]));
            rm = fmaxf(rm, __shfl_xor_sync(0xffffffffu, rm, 1));
            rm = fmaxf(rm, __shfl_xor_sync(0xffffffffu, rm, 2));
            float mn = fmaxf(m_s[j], rm);
            float corr = __expf(m_s[j] - mn);
            float ps = 0.0f;
#pragma unroll
            for (int nt = 0; nt < 8; ++nt) {
                float p0 = __expf(s[nt][j2] - mn);
                float p1 = __expf(s[nt][j2 + 1] - mn);
                s[nt][j2] = p0; s[nt][j2 + 1] = p1;
                ps += p0 + p1;
            }
            ps += __shfl_xor_sync(0xffffffffu, ps, 1);
            ps += __shfl_xor_sync(0xffffffffu, ps, 2);
            l_s[j] = l_s[j] * corr + ps;
            m_s[j] = mn;
#pragma unroll
            for (int nt = 0; nt < 8; ++nt) {
                o[nt][j2] *= corr;
                o[nt][j2 + 1] *= corr;
            }
        }

        // ---- O += P @ V ----
#pragma unroll
        for (int kt = 0; kt < 4; ++kt) {
            uint32_t ah[4];
            ah[0] = pack1h(s[2 * kt][0], s[2 * kt][1]);
            ah[1] = pack1h(s[2 * kt][2], s[2 * kt][3]);
            ah[2] = pack1h(s[2 * kt + 1][0], s[2 * kt + 1][1]);
            ah[3] = pack1h(s[2 * kt + 1][2], s[2 * kt + 1][3]);

            uint32_t vf[4][4];
#pragma unroll
            for (int g = 0; g < 4; ++g)
                ldm_x4_t(vf[g], kvb + FV_OFF + (uint32_t)kt * (16 * FROWB) + (uint32_t)g * 32 + v_off);
#pragma unroll
            for (int nt = 0; nt < 8; ++nt)
                mma_f16(o[nt], ah, &vf[nt >> 1][(nt & 1) * 2]);
        }
        __syncthreads();
    }

    // ---- epilogue: normalize, store fp16 ----
#pragma unroll
    for (int j = 0; j < 2; ++j) {
        float inv = 1.0f / l_s[j];
        size_t rowoff = (size_t)(b * LL + xr + j * 8) * DMODEL + h * DD + (lane & 3) * 2;
#pragma unroll
        for (int nt = 0; nt < 8; ++nt) {
            *(uint32_t*)(Oh + rowoff + nt * 8) =
                pack1h(o[nt][j * 2] * inv, o[nt][j * 2 + 1] * inv);
        }
    }
}

// ================================ launch ======================================
extern "C" void kernel_launch(void* const* d_in, const int* in_sizes, int n_in,
                              void* d_out, int out_size)
{
    const float* primary = (const float*)d_in[0];
    const float* context = (const float*)d_in[1];
    const int*   pmask   = (const int*)d_in[2];
    const int*   amask   = (const int*)d_in[3];
    const float* W_qs    = (const float*)d_in[4];
    const float* W_ks    = (const float*)d_in[5];
    const float* W_vs    = (const float*)d_in[6];
    const float* W_o     = (const float*)d_in[7];
    const float* b_o     = (const float*)d_in[8];
    float* out = (float*)d_out;

    __half *pH, *cH, *aH, *QH, *KH, *VH, *qH, *kH, *vH, *oH;
    cudaGetSymbolAddress((void**)&pH, g_prim_hi);
    cudaGetSymbolAddress((void**)&cH, g_ctx_hi);
    cudaGetSymbolAddress((void**)&aH, g_att_hi);
    cudaGetSymbolAddress((void**)&QH, g_Qhi);
    cudaGetSymbolAddress((void**)&KH, g_Khi);
    cudaGetSymbolAddress((void**)&VH, g_Vhi);
    cudaGetSymbolAddress((void**)&qH, g_WqT_hi);
    cudaGetSymbolAddress((void**)&kH, g_WkT_hi);
    cudaGetSymbolAddress((void**)&vH, g_WvT_hi);
    cudaGetSymbolAddress((void**)&oH, g_WoT_hi);

    const int nact4 = (MROWS * DMODEL) / 4;
    split_hi_kernel<<<nact4 / 256, 256>>>(primary, pH, nact4);
    split_hi_kernel<<<nact4 / 256, 256>>>(context, cH, nact4);
    dim3 tb(32, 8), tg(DMODEL / 32, DMODEL / 32);
    split_T_kernel<<<tg, tb>>>(W_qs, qH, DMODEL, DMODEL);
    split_T_kernel<<<tg, tb>>>(W_ks, kH, DMODEL, DMODEL);
    split_T_kernel<<<tg, tb>>>(W_vs, vH, DMODEL, DMODEL);
    split_T_kernel<<<tg, tb>>>(W_o,  oH, DMODEL, DMODEL);

    size_t gsm = 2 * STAGE_P;   // 61440
    cudaFuncSetAttribute(gemm_f16<0>, cudaFuncAttributeMaxDynamicSharedMemorySize, (int)gsm);
    cudaFuncSetAttribute(gemm_f16<1>, cudaFuncAttributeMaxDynamicSharedMemorySize, (int)gsm);
    dim3 gg(DMODEL / 128, MROWS / 256);   // (8, 16)

    gemm_f16<1><<<gg, 512, gsm>>>(pH, qH, nullptr, QH, nullptr, MROWS, DMODEL, DMODEL);
    gemm_f16<1><<<gg, 512, gsm>>>(cH, kH, nullptr, KH, nullptr, MROWS, DMODEL, DMODEL);
    gemm_f16<1><<<gg, 512, gsm>>>(cH, vH, nullptr, VH, nullptr, MROWS, DMODEL, DMODEL);

    cudaFuncSetAttribute(flash_mma, cudaFuncAttributeMaxDynamicSharedMemorySize, FSMEM_TOTAL);
    flash_mma<<<dim3(LL / 256, HH, BB), 512, FSMEM_TOTAL>>>(QH, KH, VH, amask, pmask, aH);

    gemm_f16<0><<<gg, 512, gsm>>>(aH, oH, out, nullptr, b_o, MROWS, DMODEL, DMODEL);
}

// round 9
// speedup vs baseline: 5.0397x; 1.0013x over previous
#include <cuda_runtime.h>
#include <cuda_fp16.h>
#include <math.h>
#include <stdint.h>

// Problem constants
#define BB 2
#define LL 2048
#define HH 16
#define DD 64
#define DMODEL 1024
#define MROWS (BB*LL)          // 4096

// ---------------- scratch (device globals: no allocations allowed) -------------
__device__ __align__(256) __half g_prim_hi[(size_t)MROWS * DMODEL];
__device__ __align__(256) __half g_ctx_hi [(size_t)MROWS * DMODEL];
__device__ __align__(256) __half g_Qhi[(size_t)MROWS * DMODEL];
__device__ __align__(256) __half g_Khi[(size_t)MROWS * DMODEL];
__device__ __align__(256) __half g_Vhi[(size_t)MROWS * DMODEL];
__device__ __align__(256) __half g_att_hi[(size_t)MROWS * DMODEL];
// transposed weights [N,K] K-major (fp16)
__device__ __align__(256) __half g_WqT_hi[(size_t)DMODEL * DMODEL];
__device__ __align__(256) __half g_WkT_hi[(size_t)DMODEL * DMODEL];
__device__ __align__(256) __half g_WvT_hi[(size_t)DMODEL * DMODEL];
__device__ __align__(256) __half g_WoT_hi[(size_t)DMODEL * DMODEL];

// ============================== PTX helpers ===================================
__device__ __forceinline__ uint32_t smem_u32(const void* p) {
    uint32_t a;
    asm("{ .reg .u64 t; cvta.to.shared.u64 t, %1; cvt.u32.u64 %0, t; }" : "=r"(a) : "l"(p));
    return a;
}
__device__ __forceinline__ void cp_async16(uint32_t sdst, const void* gsrc) {
    asm volatile("cp.async.cg.shared.global [%0], [%1], 16;" :: "r"(sdst), "l"(gsrc));
}
#define CP_COMMIT() asm volatile("cp.async.commit_group;" ::: "memory")
#define CP_WAIT(n)  asm volatile("cp.async.wait_group %0;" :: "n"(n) : "memory")

__device__ __forceinline__ void ldm_x4(uint32_t* r, uint32_t addr) {
    asm volatile("ldmatrix.sync.aligned.m8n8.x4.shared.b16 {%0,%1,%2,%3}, [%4];"
        : "=r"(r[0]), "=r"(r[1]), "=r"(r[2]), "=r"(r[3]) : "r"(addr));
}
__device__ __forceinline__ void ldm_x4_t(uint32_t* r, uint32_t addr) {
    asm volatile("ldmatrix.sync.aligned.m8n8.x4.trans.shared.b16 {%0,%1,%2,%3}, [%4];"
        : "=r"(r[0]), "=r"(r[1]), "=r"(r[2]), "=r"(r[3]) : "r"(addr));
}
__device__ __forceinline__ void mma_f16(float* c, const uint32_t* a, const uint32_t* b) {
    asm volatile("mma.sync.aligned.m16n8k16.row.col.f32.f16.f16.f32 "
        "{%0,%1,%2,%3}, {%4,%5,%6,%7}, {%8,%9}, {%0,%1,%2,%3};"
        : "+f"(c[0]), "+f"(c[1]), "+f"(c[2]), "+f"(c[3])
        : "r"(a[0]), "r"(a[1]), "r"(a[2]), "r"(a[3]), "r"(b[0]), "r"(b[1]));
}
__device__ __forceinline__ uint32_t pack1h(float p0, float p1) {
    uint32_t h;
    asm("cvt.rn.f16x2.f32 %0, %1, %2;" : "=r"(h) : "f"(p1), "f"(p0));
    return h;
}

// ====================== fp32 -> fp16 conversion kernels =======================
__global__ __launch_bounds__(256)
void split_hi_kernel(const float* __restrict__ x, __half* __restrict__ hi, int n4)
{
    int i = blockIdx.x * blockDim.x + threadIdx.x;
    if (i >= n4) return;
    float4 v = *(const float4*)(x + (size_t)i * 4);
    __half h[4] = {__float2half_rn(v.x), __float2half_rn(v.y),
                   __float2half_rn(v.z), __float2half_rn(v.w)};
    *(uint2*)(hi + (size_t)i * 4) = *(uint2*)h;
}

// W[K,N] -> W^T[N,K] fp16
__global__ __launch_bounds__(256)
void split_T_kernel(const float* __restrict__ W, __half* __restrict__ hiT, int K, int N)
{
    __shared__ float t[32][33];
    int k0 = blockIdx.y * 32, n0 = blockIdx.x * 32;
    int tx = threadIdx.x, ty = threadIdx.y;
#pragma unroll
    for (int j = 0; j < 4; ++j)
        t[ty + j * 8][tx] = W[(size_t)(k0 + ty + j * 8) * N + n0 + tx];
    __syncthreads();
#pragma unroll
    for (int j = 0; j < 4; ++j) {
        size_t off = (size_t)(n0 + ty + j * 8) * K + k0 + tx;
        hiT[off] = __float2half_rn(t[tx][ty + j * 8]);
    }
}

// ====================== mma.sync fp16 GEMM ====================================
// C = A[M,K] @ B^T, B stored [N,K] K-major.
// CTA 256x128, 512 threads (16 warps 4x4, warp tile 64x32), BK=32, double buffer.
#define GBK 32
#define TROW_B 80
#define OFF_A  0                   // 256*80 = 20480
#define OFF_B  20480               // 128*80 = 10240
#define STAGE_P 30720

// OM: 0 = fp32 C + bias, 1 = f16 out
template <int OM>
__global__ __launch_bounds__(512, 1)
void gemm_f16(const __half* __restrict__ A, const __half* __restrict__ B,
              float* __restrict__ C, __half* __restrict__ Ch,
              const float* __restrict__ bias, int M, int N, int K)
{
    extern __shared__ char smem[];
    const uint32_t sb = smem_u32(smem);

    const int tid = threadIdx.x;
    const int wid = tid >> 5;
    const int lane = tid & 31;
    const int warp_m = wid >> 2;
    const int warp_n = wid & 3;
    const int bn = blockIdx.x * 128;
    const int bm = blockIdx.y * 256;

    const __half* aG = A + (size_t)bm * K;
    const __half* bG = B + (size_t)bn * K;

    float acc[4][4][4];
#pragma unroll
    for (int mt = 0; mt < 4; ++mt)
#pragma unroll
        for (int nt = 0; nt < 4; ++nt)
#pragma unroll
            for (int r = 0; r < 4; ++r) acc[mt][nt][r] = 0.0f;

    const int nch = K / GBK;

    const uint32_t a_row = (lane & 7) + ((lane >> 3) & 1) * 8;
    const uint32_t a_off = a_row * TROW_B + (lane >> 4) * 16;
    const uint32_t b_row = (lane & 7) + (lane >> 4) * 8;
    const uint32_t b_off = b_row * TROW_B + ((lane >> 3) & 1) * 16;

    auto load_chunk = [&](int stage, int k0) {
        uint32_t base = sb + (uint32_t)stage * STAGE_P;
        // A: 1024 16B lines, 2 per thread
#pragma unroll
        for (int t = 0; t < 2; ++t) {
            int l = tid * 2 + t;
            int row = l >> 2, cb = l & 3;
            cp_async16(base + OFF_A + (uint32_t)row * TROW_B + cb * 16,
                       aG + (size_t)row * K + k0 + cb * 8);
        }
        // B: 512 lines, 1 per thread
        {
            int row = tid >> 2, cb = tid & 3;
            cp_async16(base + OFF_B + (uint32_t)row * TROW_B + cb * 16,
                       bG + (size_t)row * K + k0 + cb * 8);
        }
        CP_COMMIT();
    };

    load_chunk(0, 0);

    for (int i = 0; i < nch; ++i) {
        if (i + 1 < nch) {
            load_chunk((i + 1) & 1, (i + 1) * GBK);
            CP_WAIT(1);
        } else {
            CP_WAIT(0);
        }
        __syncthreads();

        uint32_t base = sb + (uint32_t)(i & 1) * STAGE_P;
        uint32_t aB = base + OFF_A + warp_m * 64 * TROW_B + a_off;
        uint32_t bB = base + OFF_B + warp_n * 32 * TROW_B + b_off;

#pragma unroll
        for (int ks = 0; ks < 2; ++ks) {
            uint32_t aF[4][4], bF[2][4];
#pragma unroll
            for (int mt = 0; mt < 4; ++mt)
                ldm_x4(aF[mt], aB + mt * 16 * TROW_B + ks * 32);
#pragma unroll
            for (int n16 = 0; n16 < 2; ++n16)
                ldm_x4(bF[n16], bB + n16 * 16 * TROW_B + ks * 32);
#pragma unroll
            for (int mt = 0; mt < 4; ++mt)
#pragma unroll
                for (int nt = 0; nt < 4; ++nt)
                    mma_f16(acc[mt][nt], aF[mt], &bF[nt >> 1][(nt & 1) * 2]);
        }
        __syncthreads();
    }

    const int r0 = bm + warp_m * 64 + (lane >> 2);
    const int c0 = bn + warp_n * 32 + (lane & 3) * 2;
#pragma unroll
    for (int mt = 0; mt < 4; ++mt) {
#pragma unroll
        for (int nt = 0; nt < 4; ++nt) {
            int col = c0 + nt * 8;
            if (OM == 0) {
                float bx = bias[col], by = bias[col + 1];
                float2 v0 = make_float2(acc[mt][nt][0] + bx, acc[mt][nt][1] + by);
                float2 v1 = make_float2(acc[mt][nt][2] + bx, acc[mt][nt][3] + by);
                *(float2*)(C + (size_t)(r0 + mt * 16) * N + col) = v0;
                *(float2*)(C + (size_t)(r0 + mt * 16 + 8) * N + col) = v1;
            } else {
                *(uint32_t*)(Ch + (size_t)(r0 + mt * 16) * N + col) =
                    pack1h(acc[mt][nt][0], acc[mt][nt][1]);
                *(uint32_t*)(Ch + (size_t)(r0 + mt * 16 + 8) * N + col) =
                    pack1h(acc[mt][nt][2], acc[mt][nt][3]);
            }
        }
    }
}

// ===================== Flash attention on mma.sync (fp16) =====================
// CTA: 256 queries x one (b,h), 512 threads (16 warps x 16 rows).
// S = Q @ K^T (1 MMA set), fp32 softmax, O += P @ V (1 MMA set).
#define FROWB 144
#define FQ_HI 0                    // 256*144 = 36864
#define FSTG_OFF 36864
#define FSTG_SZ 18432              // 2 arrays * 64*144
#define FK_OFF 0
#define FV_OFF 9216
#define FSMEM_TOTAL (FSTG_OFF + 2 * FSTG_SZ)   // 73728

__global__ __launch_bounds__(512, 1)
void flash_mma(const __half* __restrict__ Qh,
               const __half* __restrict__ Kh, const __half* __restrict__ Vh,
               const int* __restrict__ am, const int* __restrict__ pmk,
               __half* __restrict__ Oh)
{
    extern __shared__ char smem[];
    const uint32_t sb = smem_u32(smem);
    const int tid = threadIdx.x, wid = tid >> 5, lane = tid & 31;
    const int qb = (int)gridDim.x - 1 - (int)blockIdx.x;
    const int h = blockIdx.y, b = blockIdx.z;
    const int x0 = qb * 256;

    // Q tile: 2048 lines, 4 per thread
#pragma unroll
    for (int t = 0; t < 4; ++t) {
        int l = tid + t * 512;
        int r = l >> 3, c = l & 7;
        cp_async16(sb + FQ_HI + (uint32_t)r * FROWB + c * 16,
                   Qh + (size_t)(b * LL + x0 + r) * DMODEL + h * DD + c * 8);
    }
    auto load_kv = [&](int stg, int z0) {
        uint32_t base = sb + FSTG_OFF + (uint32_t)stg * FSTG_SZ;
        // K + V: 1024 lines, 2 per thread
#pragma unroll
        for (int t = 0; t < 2; ++t) {
            int l = tid + t * 512;
            int arr = l >> 9, r = (l >> 3) & 63, c = l & 7;
            const __half* src = arr ? Vh : Kh;
            cp_async16(base + (uint32_t)arr * 9216 + (uint32_t)r * FROWB + c * 16,
                       src + (size_t)(b * LL + z0 + r) * DMODEL + h * DD + c * 8);
        }
        CP_COMMIT();
    };
    load_kv(0, 0);

    const uint32_t a_row = (lane & 7) + ((lane >> 3) & 1) * 8;
    const uint32_t a_base = (uint32_t)(wid * 16 + a_row) * FROWB + (lane >> 4) * 16;
    const uint32_t b_row = (lane & 7) + (lane >> 4) * 8;
    const uint32_t b_off = b_row * FROWB + ((lane >> 3) & 1) * 16;
    const int g2 = lane >> 3;
    const uint32_t v_off = (uint32_t)((g2 & 1) * 8 + (lane & 7)) * FROWB + (g2 >> 1) * 16;

    const int xr = x0 + wid * 16 + (lane >> 2);
    const int2* am0 = (const int2*)am + (size_t)(b * LL + xr) * (LL / 2);
    const int2* am1 = am0 + (size_t)8 * (LL / 2);
    const int2* pm2 = (const int2*)pmk + (size_t)b * (LL / 2);

    float m_s[2] = {-3.0e38f, -3.0e38f};
    float l_s[2] = {0.0f, 0.0f};
    float o[8][4];
#pragma unroll
    for (int nt = 0; nt < 8; ++nt)
#pragma unroll
        for (int r = 0; r < 4; ++r) o[nt][r] = 0.0f;

    const float SC = 0.125f;
    const float NEG = -1000000.0f;
    const int nkb = 4 * qb + 4;

    for (int kb = 0; kb < nkb; ++kb) {
        if (kb + 1 < nkb) {
            load_kv((kb + 1) & 1, (kb + 1) * 64);
            CP_WAIT(1);
        } else {
            CP_WAIT(0);
        }
        __syncthreads();

        const uint32_t kvb = sb + FSTG_OFF + (uint32_t)(kb & 1) * FSTG_SZ;

        // ---- S = Q @ K^T ----
        float s[8][4];
#pragma unroll
        for (int nt = 0; nt < 8; ++nt)
#pragma unroll
            for (int r = 0; r < 4; ++r) s[nt][r] = 0.0f;

#pragma unroll
        for (int kt = 0; kt < 4; ++kt) {
            uint32_t qf[4];
            ldm_x4(qf, sb + FQ_HI + a_base + kt * 32);
            uint32_t kf[4][4];
#pragma unroll
            for (int g = 0; g < 4; ++g)
                ldm_x4(kf[g], kvb + FK_OFF + (uint32_t)g * (16 * FROWB) + b_off + kt * 32);
#pragma unroll
            for (int nt = 0; nt < 8; ++nt)
                mma_f16(s[nt], qf, &kf[nt >> 1][(nt & 1) * 2]);
        }

        // ---- scale + masks (real masks only near the diagonal) ----
        const int z0 = kb * 64;
        if (z0 + 63 > x0) {
            const int ci = (z0 >> 1) + (lane & 3);
#pragma unroll
            for (int nt = 0; nt < 8; ++nt) {
                int2 pm = pm2[ci + nt * 4];
                int2 u0 = am0[ci + nt * 4];
                int2 u1 = am1[ci + nt * 4];
                s[nt][0] = (u0.x != 0 && pm.x != 0) ? s[nt][0] * SC : NEG;
                s[nt][1] = (u0.y != 0 && pm.y != 0) ? s[nt][1] * SC : NEG;
                s[nt][2] = (u1.x != 0 && pm.x != 0) ? s[nt][2] * SC : NEG;
                s[nt][3] = (u1.y != 0 && pm.y != 0) ? s[nt][3] * SC : NEG;
            }
        } else {
#pragma unroll
            for (int nt = 0; nt < 8; ++nt) {
                s[nt][0] *= SC; s[nt][1] *= SC; s[nt][2] *= SC; s[nt][3] *= SC;
            }
        }

        // ---- online softmax ----
#pragma unroll
        for (int j = 0; j < 2; ++j) {
            const int j2 = j * 2;
            float rm = NEG;
#pragma unroll
            for (int nt = 0; nt < 8; ++nt)
                rm = fmaxf(rm, fmaxf(s[nt][j2], s[nt][j2 + 1]));
            rm = fmaxf(rm, __shfl_xor_sync(0xffffffffu, rm, 1));
            rm = fmaxf(rm, __shfl_xor_sync(0xffffffffu, rm, 2));
            float mn = fmaxf(m_s[j], rm);
            float corr = __expf(m_s[j] - mn);
            float ps = 0.0f;
#pragma unroll
            for (int nt = 0; nt < 8; ++nt) {
                float p0 = __expf(s[nt][j2] - mn);
                float p1 = __expf(s[nt][j2 + 1] - mn);
                s[nt][j2] = p0; s[nt][j2 + 1] = p1;
                ps += p0 + p1;
            }
            ps += __shfl_xor_sync(0xffffffffu, ps, 1);
            ps += __shfl_xor_sync(0xffffffffu, ps, 2);
            l_s[j] = l_s[j] * corr + ps;
            m_s[j] = mn;
#pragma unroll
            for (int nt = 0; nt < 8; ++nt) {
                o[nt][j2] *= corr;
                o[nt][j2 + 1] *= corr;
            }
        }

        // ---- O += P @ V ----
#pragma unroll
        for (int kt = 0; kt < 4; ++kt) {
            uint32_t ah[4];
            ah[0] = pack1h(s[2 * kt][0], s[2 * kt][1]);
            ah[1] = pack1h(s[2 * kt][2], s[2 * kt][3]);
            ah[2] = pack1h(s[2 * kt + 1][0], s[2 * kt + 1][1]);
            ah[3] = pack1h(s[2 * kt + 1][2], s[2 * kt + 1][3]);

            uint32_t vf[4][4];
#pragma unroll
            for (int g = 0; g < 4; ++g)
                ldm_x4_t(vf[g], kvb + FV_OFF + (uint32_t)kt * (16 * FROWB) + (uint32_t)g * 32 + v_off);
#pragma unroll
            for (int nt = 0; nt < 8; ++nt)
                mma_f16(o[nt], ah, &vf[nt >> 1][(nt & 1) * 2]);
        }
        __syncthreads();
    }

    // ---- epilogue: normalize, store fp16 ----
#pragma unroll
    for (int j = 0; j < 2; ++j) {
        float inv = 1.0f / l_s[j];
        size_t rowoff = (size_t)(b * LL + xr + j * 8) * DMODEL + h * DD + (lane & 3) * 2;
#pragma unroll
        for (int nt = 0; nt < 8; ++nt) {
            *(uint32_t*)(Oh + rowoff + nt * 8) =
                pack1h(o[nt][j * 2] * inv, o[nt][j * 2 + 1] * inv);
        }
    }
}

// ================================ launch ======================================
extern "C" void kernel_launch(void* const* d_in, const int* in_sizes, int n_in,
                              void* d_out, int out_size)
{
    const float* primary = (const float*)d_in[0];
    const float* context = (const float*)d_in[1];
    const int*   pmask   = (const int*)d_in[2];
    const int*   amask   = (const int*)d_in[3];
    const float* W_qs    = (const float*)d_in[4];
    const float* W_ks    = (const float*)d_in[5];
    const float* W_vs    = (const float*)d_in[6];
    const float* W_o     = (const float*)d_in[7];
    const float* b_o     = (const float*)d_in[8];
    float* out = (float*)d_out;

    __half *pH, *cH, *aH, *QH, *KH, *VH, *qH, *kH, *vH, *oH;
    cudaGetSymbolAddress((void**)&pH, g_prim_hi);
    cudaGetSymbolAddress((void**)&cH, g_ctx_hi);
    cudaGetSymbolAddress((void**)&aH, g_att_hi);
    cudaGetSymbolAddress((void**)&QH, g_Qhi);
    cudaGetSymbolAddress((void**)&KH, g_Khi);
    cudaGetSymbolAddress((void**)&VH, g_Vhi);
    cudaGetSymbolAddress((void**)&qH, g_WqT_hi);
    cudaGetSymbolAddress((void**)&kH, g_WkT_hi);
    cudaGetSymbolAddress((void**)&vH, g_WvT_hi);
    cudaGetSymbolAddress((void**)&oH, g_WoT_hi);

    const int nact4 = (MROWS * DMODEL) / 4;
    split_hi_kernel<<<nact4 / 256, 256>>>(primary, pH, nact4);
    split_hi_kernel<<<nact4 / 256, 256>>>(context, cH, nact4);
    dim3 tb(32, 8), tg(DMODEL / 32, DMODEL / 32);
    split_T_kernel<<<tg, tb>>>(W_qs, qH, DMODEL, DMODEL);
    split_T_kernel<<<tg, tb>>>(W_ks, kH, DMODEL, DMODEL);
    split_T_kernel<<<tg, tb>>>(W_vs, vH, DMODEL, DMODEL);
    split_T_kernel<<<tg, tb>>>(W_o,  oH, DMODEL, DMODEL);

    size_t gsm = 2 * STAGE_P;   // 61440
    cudaFuncSetAttribute(gemm_f16<0>, cudaFuncAttributeMaxDynamicSharedMemorySize, (int)gsm);
    cudaFuncSetAttribute(gemm_f16<1>, cudaFuncAttributeMaxDynamicSharedMemorySize, (int)gsm);
    dim3 gg(DMODEL / 128, MROWS / 256);   // (8, 16)

    gemm_f16<1><<<gg, 512, gsm>>>(pH, qH, nullptr, QH, nullptr, MROWS, DMODEL, DMODEL);
    gemm_f16<1><<<gg, 512, gsm>>>(cH, kH, nullptr, KH, nullptr, MROWS, DMODEL, DMODEL);
    gemm_f16<1><<<gg, 512, gsm>>>(cH, vH, nullptr, VH, nullptr, MROWS, DMODEL, DMODEL);

    cudaFuncSetAttribute(flash_mma, cudaFuncAttributeMaxDynamicSharedMemorySize, FSMEM_TOTAL);
    flash_mma<<<dim3(LL / 256, HH, BB), 512, FSMEM_TOTAL>>>(QH, KH, VH, amask, pmask, aH);

    gemm_f16<0><<<gg, 512, gsm>>>(aH, oH, out, nullptr, b_o, MROWS, DMODEL, DMODEL);
}